// round 13
// baseline (speedup 1.0000x reference)
#include <cuda_runtime.h>
#include <cstdint>
#include <math.h>

// Problem constants
#define BB    32
#define NQ    197
#define NV    1568
#define DIMD  768
#define HH    12
#define FF    8
#define NKC   196
#define NOUT  1569
#define BHN   384
#define KDIM  768

// ---------------- scratch (device globals) ----------------
__device__ float g_q[(size_t)BHN * NQ * 64];
__device__ float g_k[(size_t)BHN * NV * 64];
__device__ float g_v[(size_t)BHN * NV * 64];
__device__ float g_att[(size_t)BHN * NOUT * 64];
__device__ float g_wqT[768 * 768];      // pair-interleaved [N][K], tf32-rounded
__device__ float g_wkvT[1536 * 768];
__device__ float g_wpT[768 * 768];

// ======================= helpers =======================
__device__ __forceinline__ uint32_t smem_to_u32(const void* p) {
    uint32_t a;
    asm("{ .reg .u64 t; cvta.to.shared.u64 t, %1; cvt.u32.u64 %0, t; }" : "=r"(a) : "l"(p));
    return a;
}
__device__ __forceinline__ uint32_t to_tf32_rn(float x) {
    uint32_t r;
    asm("cvt.rn.tf32.f32 %0, %1;" : "=r"(r) : "f"(x));
    return r;
}
__device__ __forceinline__ float rnd_tf32(float x) { return __uint_as_float(to_tf32_rn(x)); }
__device__ __forceinline__ float4 f4_rnd(float4 v) {
    v.x = rnd_tf32(v.x); v.y = rnd_tf32(v.y); v.z = rnd_tf32(v.z); v.w = rnd_tf32(v.w);
    return v;
}
__device__ __forceinline__ int p8(int k) { return (k & ~7) | ((k & 3) << 1) | ((k >> 2) & 1); }
__device__ __forceinline__ void sts_pair8(float* dst, float4 v0, float4 v1) {
    *(float4*)dst       = make_float4(v0.x, v1.x, v0.y, v1.y);
    *(float4*)(dst + 4) = make_float4(v0.z, v1.z, v0.w, v1.w);
}
__device__ __forceinline__ void cp_async16(uint32_t smem_addr, const void* gptr) {
    asm volatile("cp.async.cg.shared.global [%0], [%1], 16;"
                 :: "r"(smem_addr), "l"(gptr));
}
__device__ __forceinline__ void cp_async16p(uint32_t smem_addr, const void* gptr, bool pred) {
    int sz = pred ? 16 : 0;
    asm volatile("cp.async.cg.shared.global [%0], [%1], 16, %2;"
                 :: "r"(smem_addr), "l"(gptr), "r"(sz));
}
#define CP_COMMIT() asm volatile("cp.async.commit_group;" ::: "memory")
#define CP_WAIT(n)  asm volatile("cp.async.wait_group %0;" :: "n"(n) : "memory")

__device__ __forceinline__ void mma_tf32(float* c, const uint32_t* a, const uint32_t* b) {
    asm volatile(
        "mma.sync.aligned.m16n8k8.row.col.f32.tf32.tf32.f32 "
        "{%0,%1,%2,%3}, {%4,%5,%6,%7}, {%8,%9}, {%0,%1,%2,%3};"
        : "+f"(c[0]), "+f"(c[1]), "+f"(c[2]), "+f"(c[3])
        : "r"(a[0]), "r"(a[1]), "r"(a[2]), "r"(a[3]), "r"(b[0]), "r"(b[1]));
}

// FMA-pipe exp
__device__ __forceinline__ float fast_exp(float x) {
    x = fmaxf(x, -87.0f);
    float y = x * 1.4426950408889634f;
    float r = y + 12582912.0f;
    int   n = __float_as_int(r) - 0x4B400000;
    float f = y - (r - 12582912.0f);
    float p = 1.3333558146e-3f;
    p = fmaf(p, f, 9.6181291076e-3f);
    p = fmaf(p, f, 5.5504108664e-2f);
    p = fmaf(p, f, 2.4022650696e-1f);
    p = fmaf(p, f, 6.9314718056e-1f);
    p = fmaf(p, f, 1.0f);
    return __int_as_float(__float_as_int(p) + (n << 23));
}

// ======================= weight transpose: one launch, z selects matrix =======================
__global__ __launch_bounds__(256)
void transposeW(const float* __restrict__ Wq, const float* __restrict__ Wkv,
                const float* __restrict__ Wproj)
{
    const int which = blockIdx.z;
    const float* src = (which == 0) ? Wq : (which == 1) ? Wkv : Wproj;
    float* dst = (which == 0) ? g_wqT : (which == 1) ? g_wkvT : g_wpT;
    const int N = (which == 1) ? 1536 : 768;
    const int K = 768;

    int bx = blockIdx.x * 32;   // N block
    int by = blockIdx.y * 32;   // K block
    if (bx >= N) return;

    __shared__ float t[32][33];
    int txl = threadIdx.x & 31;
    int tyl = threadIdx.x >> 5;
#pragma unroll
    for (int j = 0; j < 32; j += 8)
        t[tyl + j][txl] = src[(size_t)(by + tyl + j) * N + bx + txl];
    __syncthreads();
#pragma unroll
    for (int j = 0; j < 32; j += 8)
        dst[(size_t)(bx + tyl + j) * K + by + p8(txl)] = rnd_tf32(t[txl][tyl + j]);
}

// ======================= mma.sync tf32 GEMM body (R12 machinery) =======================
constexpr int BM = 128, BN = 128, BK = 32;
constexpr int SKA = 36;
constexpr int SKB = 40;
constexpr int A_WORDS = BM * SKA;
constexpr int B_WORDS = BN * SKB;
constexpr int STAGE_WORDS = A_WORDS + B_WORDS;
constexpr int GEMM_SMEM = 2 * STAGE_WORDS * 4;  // 77824 bytes
constexpr int KT = KDIM / BK;

template<int MODE>
__device__ __forceinline__ void gemm_body(const float* __restrict__ A,
                                          const float* __restrict__ bias,
                                          float* __restrict__ Cout,
                                          int M, int row0, int col0, float* sm)
{
    const uint32_t sb32 = smem_to_u32(sm);
    const int tid   = threadIdx.x;
    const int warp  = tid >> 5;
    const int lane  = tid & 31;
    const int group = lane >> 2;
    const int tig   = lane & 3;
    const int wm    = warp & 3;
    const int wn    = warp >> 2;

    const float* BT = (MODE == 0) ? g_wqT : (MODE == 1) ? g_wkvT : g_wpT;

    float acc[2][8][4];
#pragma unroll
    for (int mt = 0; mt < 2; mt++)
#pragma unroll
        for (int nt = 0; nt < 8; nt++)
#pragma unroll
            for (int c = 0; c < 4; c++) acc[mt][nt][c] = 0.f;

    const int lr  = tid >> 3;
    const int lk4 = (tid & 7) << 2;

    auto load_stage = [&](int kt, int s) {
        const uint32_t aoff = sb32 + (uint32_t)(s * STAGE_WORDS) * 4;
        const uint32_t boff = sb32 + (uint32_t)(s * STAGE_WORDS + A_WORDS) * 4;
        const int k0 = kt * BK;
#pragma unroll
        for (int it = 0; it < 4; it++) {
            int r = lr + it * 32;
            int grow = row0 + r;
            bool ok = grow < M;
            int gr = ok ? grow : 0;
            const float* src;
            if (MODE == 2) {
                int b_ = gr / NOUT;
                int n_ = gr - b_ * NOUT;
                int kk = k0 + lk4;
                int h = kk >> 6, dd = kk & 63;
                src = &g_att[(((size_t)(b_ * HH + h) * NOUT + n_) << 6) + dd];
            } else {
                src = &A[(size_t)gr * KDIM + k0 + lk4];
            }
            cp_async16p(aoff + (uint32_t)(r * SKA + lk4) * 4, src, ok);
        }
#pragma unroll
        for (int it = 0; it < 4; it++) {
            int r = lr + it * 32;
            cp_async16(boff + (uint32_t)(r * SKB + lk4) * 4,
                       &BT[(size_t)(col0 + r) * KDIM + k0 + lk4]);
        }
        CP_COMMIT();
    };

    load_stage(0, 0);

    for (int kt = 0; kt < KT; kt++) {
        const int cur = kt & 1;
        if (kt + 1 < KT) {
            load_stage(kt + 1, (kt + 1) & 1);
            CP_WAIT(1);
        } else {
            CP_WAIT(0);
        }
        __syncthreads();

        const float* As = sm + cur * STAGE_WORDS;
        const float* Bs = As + A_WORDS;

#pragma unroll
        for (int ks = 0; ks < 4; ks++) {
            const int kc = ks * 8 + tig;
            const int ko = ks * 8 + 2 * tig;
            uint32_t af[2][4];
#pragma unroll
            for (int mt = 0; mt < 2; mt++) {
                int r = wm * 32 + mt * 16 + group;
                af[mt][0] = to_tf32_rn(As[r * SKA + kc]);
                af[mt][1] = to_tf32_rn(As[(r + 8) * SKA + kc]);
                af[mt][2] = to_tf32_rn(As[r * SKA + kc + 4]);
                af[mt][3] = to_tf32_rn(As[(r + 8) * SKA + kc + 4]);
            }
#pragma unroll
            for (int nt = 0; nt < 8; nt++) {
                int n = wn * 64 + nt * 8 + group;
                float2 b = *(const float2*)&Bs[n * SKB + ko];
                uint32_t bf[2] = { __float_as_uint(b.x), __float_as_uint(b.y) };
                mma_tf32(acc[0][nt], af[0], bf);
                mma_tf32(acc[1][nt], af[1], bf);
            }
        }
        __syncthreads();
    }

#pragma unroll
    for (int mt = 0; mt < 2; mt++) {
#pragma unroll
        for (int half = 0; half < 2; half++) {
            int row = row0 + wm * 32 + mt * 16 + group + half * 8;
            if (row >= M) continue;
            int b_, n_;
            if (MODE == 0) { b_ = row / NQ;   n_ = row - b_ * NQ; }
            else if (MODE == 1) { b_ = row / NV; n_ = row - b_ * NV; }
            else { b_ = 0; n_ = 0; }
#pragma unroll
            for (int nt = 0; nt < 8; nt++) {
                int col = col0 + wn * 64 + nt * 8 + tig * 2;
                float v0 = acc[mt][nt][half * 2 + 0];
                float v1 = acc[mt][nt][half * 2 + 1];
                if (MODE == 0) {
                    int h = col >> 6, dd = col & 63;
                    float2 w = make_float2(v0 * 0.125f, v1 * 0.125f);
                    *(float2*)&g_q[(((size_t)(b_ * HH + h) * NQ + n_) << 6) + dd] = w;
                } else if (MODE == 1) {
                    float2 w = make_float2(v0, v1);
                    if (col < DIMD) {
                        int h = col >> 6, dd = col & 63;
                        *(float2*)&g_k[(((size_t)(b_ * HH + h) * NV + n_) << 6) + dd] = w;
                    } else {
                        int c2 = col - DIMD;
                        int h = c2 >> 6, dd = c2 & 63;
                        *(float2*)&g_v[(((size_t)(b_ * HH + h) * NV + n_) << 6) + dd] = w;
                    }
                } else {
                    float2 w = make_float2(v0 + bias[col], v1 + bias[col + 1]);
                    *(float2*)&Cout[(size_t)row * DIMD + col] = w;
                }
            }
        }
    }
}

// fused q + kv projections: blocks [0,4704) = MODE 1, [4704,5004) = MODE 0
constexpr int G1_BLOCKS = (1536 / BN) * (BB * NV / BM);                 // 4704
constexpr int G0_BLOCKS = (768 / BN) * ((BB * NQ + BM - 1) / BM);       // 300

__global__ __launch_bounds__(256, 2)
void gemm01(const float* __restrict__ question, const float* __restrict__ x)
{
    extern __shared__ float sm[];
    int id = blockIdx.x;
    if (id < G1_BLOCKS) {
        int cb = id % (1536 / BN), rb = id / (1536 / BN);
        gemm_body<1>(x, nullptr, nullptr, BB * NV, rb * BM, cb * BN, sm);
    } else {
        int id2 = id - G1_BLOCKS;
        int cb = id2 % (768 / BN), rb = id2 / (768 / BN);
        gemm_body<0>(question, nullptr, nullptr, BB * NQ, rb * BM, cb * BN, sm);
    }
}

__global__ __launch_bounds__(256, 2)
void gemm2(const float* __restrict__ bias, float* __restrict__ Cout)
{
    extern __shared__ float sm[];
    gemm_body<2>(nullptr, bias, Cout, BB * NOUT,
                 blockIdx.y * BM, blockIdx.x * BN, sm);
}

// ======================= fused attention: fine (3072 blocks) + cls (384) =======================
constexpr int QWN = 68;
constexpr int KW  = 72;
constexpr int VWN = 72;
constexpr int SW  = 228;
constexpr int Q0_OFF = 0;
constexpr int Q1_OFF = Q0_OFF + 64 * QWN;
constexpr int K_OFF  = Q1_OFF + 64 * QWN;
constexpr int V_OFF  = K_OFF + 224 * KW;
constexpr int S_OFF  = V_OFF + 200 * VWN;
constexpr int I_OFF  = S_OFF + 64 * SW;
constexpr int FINE_SMEM = (I_OFF + 64) * 4;   // 215552 bytes

__device__ __forceinline__ void fine_body(int blk, float* smf)
{
    float* Ks = smf + K_OFF;
    float* Vn = smf + V_OFF;
    float* Ss = smf + S_OFF;
    float* Iv = smf + I_OFF;

    const int bh    = blk >> 3;
    const int f     = blk & 7;
    const int tid   = threadIdx.x;
    const int warp  = tid >> 5;
    const int lane  = tid & 31;
    const int group = lane >> 2;
    const int tig   = lane & 3;
    const int wm    = warp & 3;
    const int wn    = warp >> 2;

    const uint32_t sb32 = smem_to_u32(smf);
    const float* kg = &g_k[((size_t)bh * NV + (size_t)f * NKC) * 64];
    const float* vg = &g_v[((size_t)bh * NV + (size_t)f * NKC) * 64];
    const float* qg = &g_q[((size_t)bh * NQ + 1) * 64];

    for (int idx = tid; idx < NKC * 16; idx += 512) {
        int j = idx >> 4, c4 = (idx & 15) << 2;
        cp_async16(sb32 + (uint32_t)(V_OFF + j * VWN + c4) * 4, &vg[j * 64 + c4]);
    }
    CP_COMMIT();

    auto loadQ = [&](int qc, int buf) {
        const int rows = (qc == 3) ? (NKC - 192) : 64;
        const uint32_t qoff = sb32 + (uint32_t)((buf ? Q1_OFF : Q0_OFF)) * 4;
#pragma unroll
        for (int it = 0; it < 2; it++) {
            int idx = tid + it * 512;
            int r = idx >> 4, c4 = (idx & 15) << 2;
            cp_async16p(qoff + (uint32_t)(r * QWN + c4) * 4,
                        &qg[(size_t)(qc * 64 + r) * 64 + c4], r < rows);
        }
        CP_COMMIT();
    };
    loadQ(0, 0);

    for (int u = tid; u < 224 * 8; u += 512) {
        int r = u >> 3, g = u & 7;
        float4 v0 = make_float4(0.f, 0.f, 0.f, 0.f), v1 = v0;
        if (r < NKC) {
            v0 = f4_rnd(*(const float4*)&kg[r * 64 + g * 8]);
            v1 = f4_rnd(*(const float4*)&kg[r * 64 + g * 8 + 4]);
        }
        sts_pair8(&Ks[r * KW + g * 8], v0, v1);
    }
    for (int idx = tid; idx < 4 * 18; idx += 512) {
        int r = 196 + idx / 18, c4 = (idx % 18) * 4;
        *(float4*)&Vn[r * VWN + c4] = make_float4(0.f, 0.f, 0.f, 0.f);
    }

    for (int qc = 0; qc < 4; qc++) {
        if (qc < 3) loadQ(qc + 1, (qc + 1) & 1);
        if (qc < 3) { CP_WAIT(1); } else { CP_WAIT(0); }
        __syncthreads();

        const float* Qc = smf + ((qc & 1) ? Q1_OFF : Q0_OFF);

        // ---- S = Q @ K^T
        {
            float acc[7][4];
#pragma unroll
            for (int nt = 0; nt < 7; nt++)
#pragma unroll
                for (int c = 0; c < 4; c++) acc[nt][c] = 0.f;

#pragma unroll
            for (int ks = 0; ks < 8; ks++) {
                const int kc = ks * 8 + tig;
                const int ko = ks * 8 + 2 * tig;
                const int r = wm * 16 + group;
                uint32_t af[4];
                af[0] = to_tf32_rn(Qc[r * QWN + kc]);
                af[1] = to_tf32_rn(Qc[(r + 8) * QWN + kc]);
                af[2] = to_tf32_rn(Qc[r * QWN + kc + 4]);
                af[3] = to_tf32_rn(Qc[(r + 8) * QWN + kc + 4]);
#pragma unroll
                for (int nt = 0; nt < 7; nt++) {
                    int n = wn * 56 + nt * 8 + group;
                    float2 b = *(const float2*)&Ks[n * KW + ko];
                    uint32_t bf[2] = { __float_as_uint(b.x), __float_as_uint(b.y) };
                    mma_tf32(acc[nt], af, bf);
                }
            }
            const int r = wm * 16 + group;
#pragma unroll
            for (int nt = 0; nt < 7; nt++) {
                int n = wn * 56 + nt * 8 + tig * 2;
                *(float2*)&Ss[r * SW + n]       = make_float2(acc[nt][0], acc[nt][1]);
                *(float2*)&Ss[(r + 8) * SW + n] = make_float2(acc[nt][2], acc[nt][3]);
            }
        }
        __syncthreads();

        // ---- softmax
        {
            float mx[4], sum[4];
#pragma unroll
            for (int rr = 0; rr < 4; rr++) mx[rr] = -1e30f;
#pragma unroll
            for (int it = 0; it < 7; it++) {
                int j = lane + it * 32;
                if (j < NKC) {
#pragma unroll
                    for (int rr = 0; rr < 4; rr++)
                        mx[rr] = fmaxf(mx[rr], Ss[(warp * 4 + rr) * SW + j]);
                }
            }
#pragma unroll
            for (int o = 16; o > 0; o >>= 1)
#pragma unroll
                for (int rr = 0; rr < 4; rr++)
                    mx[rr] = fmaxf(mx[rr], __shfl_xor_sync(0xffffffffu, mx[rr], o));
#pragma unroll
            for (int rr = 0; rr < 4; rr++) sum[rr] = 0.f;
#pragma unroll
            for (int it = 0; it < 7; it++) {
                int j = lane + it * 32;
                if (j < NKC) {
#pragma unroll
                    for (int rr = 0; rr < 4; rr++) {
                        float* sp = &Ss[(warp * 4 + rr) * SW + j];
                        float e = fast_exp(*sp - mx[rr]);
                        *sp = rnd_tf32(e);
                        sum[rr] += e;
                    }
                }
            }
#pragma unroll
            for (int o = 16; o > 0; o >>= 1)
#pragma unroll
                for (int rr = 0; rr < 4; rr++)
                    sum[rr] += __shfl_xor_sync(0xffffffffu, sum[rr], o);
            if (lane == 0) {
#pragma unroll
                for (int rr = 0; rr < 4; rr++) Iv[warp * 4 + rr] = 1.f / sum[rr];
            }
        }
        __syncthreads();

        // ---- O = P @ V
        {
            float acc[2][4];
#pragma unroll
            for (int nt = 0; nt < 2; nt++)
#pragma unroll
                for (int c = 0; c < 4; c++) acc[nt][c] = 0.f;

            for (int ks = 0; ks < 25; ks++) {
                const int kc = ks * 8 + tig;
                const int r = wm * 16 + group;
                uint32_t af[4] = {
                    __float_as_uint(Ss[r * SW + kc]),
                    __float_as_uint(Ss[(r + 8) * SW + kc]),
                    __float_as_uint(Ss[r * SW + kc + 4]),
                    __float_as_uint(Ss[(r + 8) * SW + kc + 4]) };
#pragma unroll
                for (int nt = 0; nt < 2; nt++) {
                    int n = wn * 16 + nt * 8 + group;
                    uint32_t bf[2];
                    bf[0] = to_tf32_rn(Vn[(ks * 8 + tig) * VWN + n]);
                    bf[1] = to_tf32_rn(Vn[(ks * 8 + tig + 4) * VWN + n]);
                    mma_tf32(acc[nt], af, bf);
                }
            }
#pragma unroll
            for (int half = 0; half < 2; half++) {
                int rl = wm * 16 + group + half * 8;
                int qrow = qc * 64 + rl;
                if (qrow >= NKC) continue;
                float iv = Iv[rl];
                size_t base = ((size_t)bh * NOUT + 1 + (size_t)f * NKC + qrow) * 64;
#pragma unroll
                for (int nt = 0; nt < 2; nt++) {
                    int col = wn * 16 + nt * 8 + tig * 2;
                    float2 w = make_float2(acc[nt][half * 2] * iv,
                                           acc[nt][half * 2 + 1] * iv);
                    *(float2*)&g_att[base + col] = w;
                }
            }
        }
        __syncthreads();
    }
}

__device__ __forceinline__ void cls_body(int bh, float* smf)
{
    // smem slices from the dynamic buffer (512-thread version)
    float* qsh = smf;              // 64
    float* ssh = smf + 64;         // 1568
    float* red = smf + 64 + NV;    // 64
    float* osh = red + 64;         // 8*64

    const int tid  = threadIdx.x;
    const int lane = tid & 31;
    const int warp = tid >> 5;     // 0..15

    if (tid < 64) qsh[tid] = g_q[((size_t)bh * NQ) * 64 + tid];
    __syncthreads();

    for (int j = warp; j < NV; j += 16) {
        const float* kr = &g_k[((size_t)bh * NV + j) * 64];
        float p = qsh[lane] * kr[lane] + qsh[lane + 32] * kr[lane + 32];
#pragma unroll
        for (int o = 16; o > 0; o >>= 1) p += __shfl_xor_sync(0xffffffffu, p, o);
        if (lane == 0) ssh[j] = p;
    }
    __syncthreads();

    float m = -1e30f;
    for (int j = tid; j < NV; j += 512) m = fmaxf(m, ssh[j]);
#pragma unroll
    for (int o = 16; o > 0; o >>= 1) m = fmaxf(m, __shfl_xor_sync(0xffffffffu, m, o));
    if (lane == 0) red[warp] = m;
    __syncthreads();
    if (tid == 0) {
        float mm = red[0];
        for (int w = 1; w < 16; w++) mm = fmaxf(mm, red[w]);
        red[32] = mm;
    }
    __syncthreads();
    m = red[32];

    float s = 0.f;
    for (int j = tid; j < NV; j += 512) {
        float e = fast_exp(ssh[j] - m);
        ssh[j] = e;
        s += e;
    }
#pragma unroll
    for (int o = 16; o > 0; o >>= 1) s += __shfl_xor_sync(0xffffffffu, s, o);
    if (lane == 0) red[16 + warp] = s;
    __syncthreads();
    if (tid == 0) {
        float ss = 0.f;
        for (int w = 0; w < 16; w++) ss += red[16 + w];
        red[33] = 1.f / ss;
    }
    __syncthreads();
    const float inv = red[33];

    const int g = tid >> 6, dd = tid & 63;    // 8 groups x 64 dims
    float o = 0.f;
    for (int j = g; j < NV; j += 8)
        o = fmaf(ssh[j], g_v[((size_t)bh * NV + j) * 64 + dd], o);
    osh[g * 64 + dd] = o;
    __syncthreads();
    if (tid < 64) {
        float r = 0.f;
#pragma unroll
        for (int gg = 0; gg < 8; gg++) r += osh[gg * 64 + tid];
        g_att[((size_t)bh * NOUT) * 64 + tid] = r * inv;
    }
}

__global__ __launch_bounds__(512, 1)
void attn_fused()
{
    extern __shared__ float smf[];
    if (blockIdx.x < BHN * FF) fine_body(blockIdx.x, smf);
    else                       cls_body(blockIdx.x - BHN * FF, smf);
}

// ======================= launch =======================
extern "C" void kernel_launch(void* const* d_in, const int* in_sizes, int n_in,
                              void* d_out, int out_size)
{
    const float* x        = (const float*)d_in[0];
    const float* question = (const float*)d_in[1];
    const float* Wq       = (const float*)d_in[2];
    const float* Wkv      = (const float*)d_in[3];
    const float* Wproj    = (const float*)d_in[4];
    const float* bproj    = (const float*)d_in[5];
    float* out = (float*)d_out;

    cudaFuncSetAttribute(attn_fused, cudaFuncAttributeMaxDynamicSharedMemorySize, FINE_SMEM);
    cudaFuncSetAttribute(gemm01, cudaFuncAttributeMaxDynamicSharedMemorySize, GEMM_SMEM);
    cudaFuncSetAttribute(gemm2,  cudaFuncAttributeMaxDynamicSharedMemorySize, GEMM_SMEM);

    // weight prep: one launch, z = matrix
    transposeW<<<dim3(1536 / 32, 768 / 32, 3), 256>>>(Wq, Wkv, Wproj);

    // fused q + kv projections
    gemm01<<<G1_BLOCKS + G0_BLOCKS, 256, GEMM_SMEM>>>(question, x);

    // fused fine + cls attention
    attn_fused<<<BHN * FF + BHN, 512, FINE_SMEM>>>();

    // output projection
    gemm2<<<dim3(768 / BN, (BB * NOUT + BM - 1) / BM), 256, GEMM_SMEM>>>(bproj, out);
}

// round 14
// speedup vs baseline: 1.2626x; 1.2626x over previous
#include <cuda_runtime.h>
#include <cuda_fp16.h>
#include <cstdint>
#include <math.h>

// Problem constants
#define BB    32
#define NQ    197
#define NV    1568
#define DIMD  768
#define HH    12
#define FF    8
#define NKC   196
#define NOUT  1569
#define BHN   384
#define KDIM  768

// ---------------- scratch (device globals) ----------------
__device__ float  g_q[(size_t)BHN * NQ * 64];
__device__ float  g_k[(size_t)BHN * NV * 64];
__device__ float  g_v[(size_t)BHN * NV * 64];
__device__ __half g_attH[(size_t)BHN * NOUT * 64];     // fp16, written by attention
__device__ __half g_qH[(size_t)BB * NQ * KDIM];        // question fp16, pre-scaled 0.125
__device__ __half g_xH[(size_t)BB * NV * KDIM];        // x fp16
__device__ __half g_wqTH[768 * 768];                   // W^T [N][K] fp16
__device__ __half g_wkvTH[1536 * 768];
__device__ __half g_wpTH[768 * 768];

// ======================= helpers =======================
__device__ __forceinline__ uint32_t smem_to_u32(const void* p) {
    uint32_t a;
    asm("{ .reg .u64 t; cvta.to.shared.u64 t, %1; cvt.u32.u64 %0, t; }" : "=r"(a) : "l"(p));
    return a;
}
__device__ __forceinline__ uint32_t to_tf32_rn(float x) {
    uint32_t r;
    asm("cvt.rn.tf32.f32 %0, %1;" : "=r"(r) : "f"(x));
    return r;
}
__device__ __forceinline__ float rnd_tf32(float x) { return __uint_as_float(to_tf32_rn(x)); }
__device__ __forceinline__ float4 f4_rnd(float4 v) {
    v.x = rnd_tf32(v.x); v.y = rnd_tf32(v.y); v.z = rnd_tf32(v.z); v.w = rnd_tf32(v.w);
    return v;
}
__device__ __forceinline__ int p8(int k) { return (k & ~7) | ((k & 3) << 1) | ((k >> 2) & 1); }
__device__ __forceinline__ void sts_pair8(float* dst, float4 v0, float4 v1) {
    *(float4*)dst       = make_float4(v0.x, v1.x, v0.y, v1.y);
    *(float4*)(dst + 4) = make_float4(v0.z, v1.z, v0.w, v1.w);
}
__device__ __forceinline__ void cp_async16(uint32_t smem_addr, const void* gptr) {
    asm volatile("cp.async.cg.shared.global [%0], [%1], 16;"
                 :: "r"(smem_addr), "l"(gptr));
}
__device__ __forceinline__ void cp_async16p(uint32_t smem_addr, const void* gptr, bool pred) {
    int sz = pred ? 16 : 0;
    asm volatile("cp.async.cg.shared.global [%0], [%1], 16, %2;"
                 :: "r"(smem_addr), "l"(gptr), "r"(sz));
}
#define CP_COMMIT() asm volatile("cp.async.commit_group;" ::: "memory")
#define CP_WAIT(n)  asm volatile("cp.async.wait_group %0;" :: "n"(n) : "memory")

// tf32 m16n8k8 (attention)
__device__ __forceinline__ void mma_tf32(float* c, const uint32_t* a, const uint32_t* b) {
    asm volatile(
        "mma.sync.aligned.m16n8k8.row.col.f32.tf32.tf32.f32 "
        "{%0,%1,%2,%3}, {%4,%5,%6,%7}, {%8,%9}, {%0,%1,%2,%3};"
        : "+f"(c[0]), "+f"(c[1]), "+f"(c[2]), "+f"(c[3])
        : "r"(a[0]), "r"(a[1]), "r"(a[2]), "r"(a[3]), "r"(b[0]), "r"(b[1]));
}
// fp16 m16n8k16 (projection GEMMs)
__device__ __forceinline__ void mma_f16(float* c, const uint32_t* a, const uint32_t* b) {
    asm volatile(
        "mma.sync.aligned.m16n8k16.row.col.f32.f16.f16.f32 "
        "{%0,%1,%2,%3}, {%4,%5,%6,%7}, {%8,%9}, {%0,%1,%2,%3};"
        : "+f"(c[0]), "+f"(c[1]), "+f"(c[2]), "+f"(c[3])
        : "r"(a[0]), "r"(a[1]), "r"(a[2]), "r"(a[3]), "r"(b[0]), "r"(b[1]));
}

// FMA-pipe exp
__device__ __forceinline__ float fast_exp(float x) {
    x = fmaxf(x, -87.0f);
    float y = x * 1.4426950408889634f;
    float r = y + 12582912.0f;
    int   n = __float_as_int(r) - 0x4B400000;
    float f = y - (r - 12582912.0f);
    float p = 1.3333558146e-3f;
    p = fmaf(p, f, 9.6181291076e-3f);
    p = fmaf(p, f, 5.5504108664e-2f);
    p = fmaf(p, f, 2.4022650696e-1f);
    p = fmaf(p, f, 6.9314718056e-1f);
    p = fmaf(p, f, 1.0f);
    return __int_as_float(__float_as_int(p) + (n << 23));
}

// ======================= fp32 -> fp16 convert (+scale), 8 elems/thread =======================
__global__ __launch_bounds__(256)
void convertH(const float* __restrict__ src, __half* __restrict__ dst,
              int n8, float scale)
{
    int i = blockIdx.x * 256 + threadIdx.x;
    if (i >= n8) return;
    const float4* s = (const float4*)src + (size_t)i * 2;
    float4 v0 = s[0], v1 = s[1];
    __half2 h0 = __floats2half2_rn(v0.x * scale, v0.y * scale);
    __half2 h1 = __floats2half2_rn(v0.z * scale, v0.w * scale);
    __half2 h2 = __floats2half2_rn(v1.x * scale, v1.y * scale);
    __half2 h3 = __floats2half2_rn(v1.z * scale, v1.w * scale);
    uint4 o;
    o.x = *(uint32_t*)&h0; o.y = *(uint32_t*)&h1;
    o.z = *(uint32_t*)&h2; o.w = *(uint32_t*)&h3;
    ((uint4*)dst)[i] = o;
}

// ======================= weight transpose -> fp16 [N][K] (one launch, z selects) ==========
__global__ __launch_bounds__(256)
void transposeW(const float* __restrict__ Wq, const float* __restrict__ Wkv,
                const float* __restrict__ Wproj)
{
    const int which = blockIdx.z;
    const float* src = (which == 0) ? Wq : (which == 1) ? Wkv : Wproj;
    __half* dst = (which == 0) ? g_wqTH : (which == 1) ? g_wkvTH : g_wpTH;
    const int N = (which == 1) ? 1536 : 768;
    const int K = 768;

    int bx = blockIdx.x * 32;
    int by = blockIdx.y * 32;
    if (bx >= N) return;

    __shared__ float t[32][33];
    int txl = threadIdx.x & 31;
    int tyl = threadIdx.x >> 5;
#pragma unroll
    for (int j = 0; j < 32; j += 8)
        t[tyl + j][txl] = src[(size_t)(by + tyl + j) * N + bx + txl];
    __syncthreads();
#pragma unroll
    for (int j = 0; j < 32; j += 8)
        dst[(size_t)(bx + tyl + j) * K + by + txl] = __float2half(t[txl][tyl + j]);
}

// ======================= fp16 mma.sync GEMM =======================
// Both operands fp16 in gmem; cp.async raw copies; stride 40 halfs (20 words: bank-clean).
constexpr int BM = 128, BN = 128, BK = 32;     // BK in halfs (2 ksteps of 16)
constexpr int SK_H = 40;                        // halfs per row in smem
constexpr int OP_HALFS = 128 * SK_H;            // 5120 halfs = 10240 B per operand
constexpr int STAGE_HALFS = 2 * OP_HALFS;       // 20480 B per stage
constexpr int GEMM_SMEM = 2 * STAGE_HALFS * 2;  // 40960 bytes
constexpr int KT = KDIM / BK;                   // 24

template<int MODE>
__global__ __launch_bounds__(256, 2)
void gemm_tc(const __half* __restrict__ A, const float* __restrict__ bias,
             float* __restrict__ Cout, int M)
{
    extern __shared__ __half smh[];
    const uint32_t sb32 = smem_to_u32(smh);
    const int tid   = threadIdx.x;
    const int warp  = tid >> 5;
    const int lane  = tid & 31;
    const int group = lane >> 2;
    const int tig   = lane & 3;
    const int wm    = warp & 3;
    const int wn    = warp >> 2;
    const int row0  = blockIdx.y * BM;
    const int col0  = blockIdx.x * BN;

    const __half* BT = (MODE == 0) ? g_wqTH : (MODE == 1) ? g_wkvTH : g_wpTH;

    float acc[2][8][4];
#pragma unroll
    for (int mt = 0; mt < 2; mt++)
#pragma unroll
        for (int nt = 0; nt < 8; nt++)
#pragma unroll
            for (int c = 0; c < 4; c++) acc[mt][nt][c] = 0.f;

    // chunk coords: 512 chunks (16B = 8 halfs) per operand tile -> 2/thread
    auto load_stage = [&](int kt, int s) {
        const uint32_t aoff = sb32 + (uint32_t)(s * STAGE_HALFS) * 2;
        const uint32_t boff = aoff + (uint32_t)OP_HALFS * 2;
        const int k0 = kt * BK;
#pragma unroll
        for (int it = 0; it < 2; it++) {
            int idx = tid + it * 256;
            int r = idx >> 2, ch = idx & 3;          // 128 rows x 4 chunks
            int grow = row0 + r;
            bool ok = grow < M;
            int gr = ok ? grow : 0;
            const __half* src;
            if (MODE == 2) {
                int b_ = gr / NOUT;
                int n_ = gr - b_ * NOUT;
                int kk = k0 + ch * 8;
                int h = kk >> 6, dd = kk & 63;
                src = &g_attH[(((size_t)(b_ * HH + h) * NOUT + n_) << 6) + dd];
            } else {
                src = &A[(size_t)gr * KDIM + k0 + ch * 8];
            }
            cp_async16p(aoff + (uint32_t)(r * SK_H + ch * 8) * 2, src, ok);
        }
#pragma unroll
        for (int it = 0; it < 2; it++) {
            int idx = tid + it * 256;
            int r = idx >> 2, ch = idx & 3;
            cp_async16(boff + (uint32_t)(r * SK_H + ch * 8) * 2,
                       &BT[(size_t)(col0 + r) * KDIM + k0 + ch * 8]);
        }
        CP_COMMIT();
    };

    load_stage(0, 0);

    for (int kt = 0; kt < KT; kt++) {
        const int cur = kt & 1;
        if (kt + 1 < KT) {
            load_stage(kt + 1, (kt + 1) & 1);
            CP_WAIT(1);
        } else {
            CP_WAIT(0);
        }
        __syncthreads();

        const __half* As = smh + cur * STAGE_HALFS;
        const __half* Bs = As + OP_HALFS;

#pragma unroll
        for (int s = 0; s < 2; s++) {           // two k16 steps per ktile
            const int kb = s * 16 + 2 * tig;
            uint32_t af[2][4];
#pragma unroll
            for (int mt = 0; mt < 2; mt++) {
                int r = wm * 32 + mt * 16 + group;
                af[mt][0] = *(const uint32_t*)&As[r * SK_H + kb];
                af[mt][1] = *(const uint32_t*)&As[(r + 8) * SK_H + kb];
                af[mt][2] = *(const uint32_t*)&As[r * SK_H + kb + 8];
                af[mt][3] = *(const uint32_t*)&As[(r + 8) * SK_H + kb + 8];
            }
#pragma unroll
            for (int nt = 0; nt < 8; nt++) {
                int n = wn * 64 + nt * 8 + group;
                uint32_t bf[2];
                bf[0] = *(const uint32_t*)&Bs[n * SK_H + kb];
                bf[1] = *(const uint32_t*)&Bs[n * SK_H + kb + 8];
                mma_f16(acc[0][nt], af[0], bf);
                mma_f16(acc[1][nt], af[1], bf);
            }
        }
        __syncthreads();
    }

    // ---- epilogue
#pragma unroll
    for (int mt = 0; mt < 2; mt++) {
#pragma unroll
        for (int half = 0; half < 2; half++) {
            int row = row0 + wm * 32 + mt * 16 + group + half * 8;
            if (row >= M) continue;
            int b_, n_;
            if (MODE == 0) { b_ = row / NQ;   n_ = row - b_ * NQ; }
            else if (MODE == 1) { b_ = row / NV; n_ = row - b_ * NV; }
            else { b_ = 0; n_ = 0; }
#pragma unroll
            for (int nt = 0; nt < 8; nt++) {
                int col = col0 + wn * 64 + nt * 8 + tig * 2;
                float v0 = acc[mt][nt][half * 2 + 0];
                float v1 = acc[mt][nt][half * 2 + 1];
                if (MODE == 0) {
                    int h = col >> 6, dd = col & 63;
                    *(float2*)&g_q[(((size_t)(b_ * HH + h) * NQ + n_) << 6) + dd] =
                        make_float2(v0, v1);    // 0.125 pre-folded into g_qH
                } else if (MODE == 1) {
                    float2 w = make_float2(v0, v1);
                    if (col < DIMD) {
                        int h = col >> 6, dd = col & 63;
                        *(float2*)&g_k[(((size_t)(b_ * HH + h) * NV + n_) << 6) + dd] = w;
                    } else {
                        int c2 = col - DIMD;
                        int h = c2 >> 6, dd = c2 & 63;
                        *(float2*)&g_v[(((size_t)(b_ * HH + h) * NV + n_) << 6) + dd] = w;
                    }
                } else {
                    float2 w = make_float2(v0 + bias[col], v1 + bias[col + 1]);
                    *(float2*)&Cout[(size_t)row * DIMD + col] = w;
                }
            }
        }
    }
}

// ======================= cls-token attention (writes fp16 g_attH) =======================
__global__ __launch_bounds__(256)
void cls_attn()
{
    __shared__ float qsh[64];
    __shared__ float ssh[NV];
    __shared__ float red[40];
    __shared__ float osh[4][64];

    const int bh   = blockIdx.x;
    const int tid  = threadIdx.x;
    const int lane = tid & 31;
    const int warp = tid >> 5;

    if (tid < 64) qsh[tid] = g_q[((size_t)bh * NQ) * 64 + tid];
    __syncthreads();

    for (int j = warp; j < NV; j += 8) {
        const float* kr = &g_k[((size_t)bh * NV + j) * 64];
        float p = qsh[lane] * kr[lane] + qsh[lane + 32] * kr[lane + 32];
#pragma unroll
        for (int o = 16; o > 0; o >>= 1) p += __shfl_xor_sync(0xffffffffu, p, o);
        if (lane == 0) ssh[j] = p;
    }
    __syncthreads();

    float m = -1e30f;
    for (int j = tid; j < NV; j += 256) m = fmaxf(m, ssh[j]);
#pragma unroll
    for (int o = 16; o > 0; o >>= 1) m = fmaxf(m, __shfl_xor_sync(0xffffffffu, m, o));
    if (lane == 0) red[warp] = m;
    __syncthreads();
    if (tid == 0) {
        float mm = red[0];
        for (int w = 1; w < 8; w++) mm = fmaxf(mm, red[w]);
        red[32] = mm;
    }
    __syncthreads();
    m = red[32];

    float s = 0.f;
    for (int j = tid; j < NV; j += 256) {
        float e = fast_exp(ssh[j] - m);
        ssh[j] = e;
        s += e;
    }
#pragma unroll
    for (int o = 16; o > 0; o >>= 1) s += __shfl_xor_sync(0xffffffffu, s, o);
    if (lane == 0) red[8 + warp] = s;
    __syncthreads();
    if (tid == 0) {
        float ss = 0.f;
        for (int w = 0; w < 8; w++) ss += red[8 + w];
        red[33] = 1.f / ss;
    }
    __syncthreads();
    const float inv = red[33];

    const int g = tid >> 6, dd = tid & 63;
    float o = 0.f;
    for (int j = g; j < NV; j += 4)
        o = fmaf(ssh[j], g_v[((size_t)bh * NV + j) * 64 + dd], o);
    osh[g][dd] = o;
    __syncthreads();
    if (tid < 64) {
        float r = (osh[0][tid] + osh[1][tid] + osh[2][tid] + osh[3][tid]) * inv;
        g_attH[((size_t)bh * NOUT) * 64 + tid] = __float2half(r);
    }
}

// ======================= fine attention — R12 version, fp16 output ===========
constexpr int QWN = 68;
constexpr int KW  = 72;
constexpr int VWN = 72;
constexpr int SW  = 228;
constexpr int Q0_OFF = 0;
constexpr int Q1_OFF = Q0_OFF + 64 * QWN;
constexpr int K_OFF  = Q1_OFF + 64 * QWN;
constexpr int V_OFF  = K_OFF + 224 * KW;
constexpr int S_OFF  = V_OFF + 200 * VWN;
constexpr int I_OFF  = S_OFF + 64 * SW;
constexpr int FINE_SMEM = (I_OFF + 64) * 4;

__global__ __launch_bounds__(512, 1)
void fine_attn()
{
    extern __shared__ float smf[];
    float* Ks = smf + K_OFF;
    float* Vn = smf + V_OFF;
    float* Ss = smf + S_OFF;
    float* Iv = smf + I_OFF;

    const int bh    = blockIdx.x >> 3;
    const int f     = blockIdx.x & 7;
    const int tid   = threadIdx.x;
    const int warp  = tid >> 5;
    const int lane  = tid & 31;
    const int group = lane >> 2;
    const int tig   = lane & 3;
    const int wm    = warp & 3;
    const int wn    = warp >> 2;

    const uint32_t sb32 = smem_to_u32(smf);
    const float* kg = &g_k[((size_t)bh * NV + (size_t)f * NKC) * 64];
    const float* vg = &g_v[((size_t)bh * NV + (size_t)f * NKC) * 64];
    const float* qg = &g_q[((size_t)bh * NQ + 1) * 64];

    for (int idx = tid; idx < NKC * 16; idx += 512) {
        int j = idx >> 4, c4 = (idx & 15) << 2;
        cp_async16(sb32 + (uint32_t)(V_OFF + j * VWN + c4) * 4, &vg[j * 64 + c4]);
    }
    CP_COMMIT();

    auto loadQ = [&](int qc, int buf) {
        const int rows = (qc == 3) ? (NKC - 192) : 64;
        const uint32_t qoff = sb32 + (uint32_t)((buf ? Q1_OFF : Q0_OFF)) * 4;
#pragma unroll
        for (int it = 0; it < 2; it++) {
            int idx = tid + it * 512;
            int r = idx >> 4, c4 = (idx & 15) << 2;
            cp_async16p(qoff + (uint32_t)(r * QWN + c4) * 4,
                        &qg[(size_t)(qc * 64 + r) * 64 + c4], r < rows);
        }
        CP_COMMIT();
    };
    loadQ(0, 0);

    for (int u = tid; u < 224 * 8; u += 512) {
        int r = u >> 3, g = u & 7;
        float4 v0 = make_float4(0.f, 0.f, 0.f, 0.f), v1 = v0;
        if (r < NKC) {
            v0 = f4_rnd(*(const float4*)&kg[r * 64 + g * 8]);
            v1 = f4_rnd(*(const float4*)&kg[r * 64 + g * 8 + 4]);
        }
        sts_pair8(&Ks[r * KW + g * 8], v0, v1);
    }
    for (int idx = tid; idx < 4 * 18; idx += 512) {
        int r = 196 + idx / 18, c4 = (idx % 18) * 4;
        *(float4*)&Vn[r * VWN + c4] = make_float4(0.f, 0.f, 0.f, 0.f);
    }

    for (int qc = 0; qc < 4; qc++) {
        if (qc < 3) loadQ(qc + 1, (qc + 1) & 1);
        if (qc < 3) { CP_WAIT(1); } else { CP_WAIT(0); }
        __syncthreads();

        const float* Qc = smf + ((qc & 1) ? Q1_OFF : Q0_OFF);

        // ---- S = Q @ K^T
        {
            float acc[7][4];
#pragma unroll
            for (int nt = 0; nt < 7; nt++)
#pragma unroll
                for (int c = 0; c < 4; c++) acc[nt][c] = 0.f;

#pragma unroll
            for (int ks = 0; ks < 8; ks++) {
                const int kc = ks * 8 + tig;
                const int ko = ks * 8 + 2 * tig;
                const int r = wm * 16 + group;
                uint32_t af[4];
                af[0] = to_tf32_rn(Qc[r * QWN + kc]);
                af[1] = to_tf32_rn(Qc[(r + 8) * QWN + kc]);
                af[2] = to_tf32_rn(Qc[r * QWN + kc + 4]);
                af[3] = to_tf32_rn(Qc[(r + 8) * QWN + kc + 4]);
#pragma unroll
                for (int nt = 0; nt < 7; nt++) {
                    int n = wn * 56 + nt * 8 + group;
                    float2 b = *(const float2*)&Ks[n * KW + ko];
                    uint32_t bf[2] = { __float_as_uint(b.x), __float_as_uint(b.y) };
                    mma_tf32(acc[nt], af, bf);
                }
            }
            const int r = wm * 16 + group;
#pragma unroll
            for (int nt = 0; nt < 7; nt++) {
                int n = wn * 56 + nt * 8 + tig * 2;
                *(float2*)&Ss[r * SW + n]       = make_float2(acc[nt][0], acc[nt][1]);
                *(float2*)&Ss[(r + 8) * SW + n] = make_float2(acc[nt][2], acc[nt][3]);
            }
        }
        __syncthreads();

        // ---- softmax
        {
            float mx[4], sum[4];
#pragma unroll
            for (int rr = 0; rr < 4; rr++) mx[rr] = -1e30f;
#pragma unroll
            for (int it = 0; it < 7; it++) {
                int j = lane + it * 32;
                if (j < NKC) {
#pragma unroll
                    for (int rr = 0; rr < 4; rr++)
                        mx[rr] = fmaxf(mx[rr], Ss[(warp * 4 + rr) * SW + j]);
                }
            }
#pragma unroll
            for (int o = 16; o > 0; o >>= 1)
#pragma unroll
                for (int rr = 0; rr < 4; rr++)
                    mx[rr] = fmaxf(mx[rr], __shfl_xor_sync(0xffffffffu, mx[rr], o));
#pragma unroll
            for (int rr = 0; rr < 4; rr++) sum[rr] = 0.f;
#pragma unroll
            for (int it = 0; it < 7; it++) {
                int j = lane + it * 32;
                if (j < NKC) {
#pragma unroll
                    for (int rr = 0; rr < 4; rr++) {
                        float* sp = &Ss[(warp * 4 + rr) * SW + j];
                        float e = fast_exp(*sp - mx[rr]);
                        *sp = rnd_tf32(e);
                        sum[rr] += e;
                    }
                }
            }
#pragma unroll
            for (int o = 16; o > 0; o >>= 1)
#pragma unroll
                for (int rr = 0; rr < 4; rr++)
                    sum[rr] += __shfl_xor_sync(0xffffffffu, sum[rr], o);
            if (lane == 0) {
#pragma unroll
                for (int rr = 0; rr < 4; rr++) Iv[warp * 4 + rr] = 1.f / sum[rr];
            }
        }
        __syncthreads();

        // ---- O = P @ V
        {
            float acc[2][4];
#pragma unroll
            for (int nt = 0; nt < 2; nt++)
#pragma unroll
                for (int c = 0; c < 4; c++) acc[nt][c] = 0.f;

            for (int ks = 0; ks < 25; ks++) {
                const int kc = ks * 8 + tig;
                const int r = wm * 16 + group;
                uint32_t af[4] = {
                    __float_as_uint(Ss[r * SW + kc]),
                    __float_as_uint(Ss[(r + 8) * SW + kc]),
                    __float_as_uint(Ss[r * SW + kc + 4]),
                    __float_as_uint(Ss[(r + 8) * SW + kc + 4]) };
#pragma unroll
                for (int nt = 0; nt < 2; nt++) {
                    int n = wn * 16 + nt * 8 + group;
                    uint32_t bf[2];
                    bf[0] = to_tf32_rn(Vn[(ks * 8 + tig) * VWN + n]);
                    bf[1] = to_tf32_rn(Vn[(ks * 8 + tig + 4) * VWN + n]);
                    mma_tf32(acc[nt], af, bf);
                }
            }
#pragma unroll
            for (int half = 0; half < 2; half++) {
                int rl = wm * 16 + group + half * 8;
                int qrow = qc * 64 + rl;
                if (qrow >= NKC) continue;
                float iv = Iv[rl];
                size_t base = ((size_t)bh * NOUT + 1 + (size_t)f * NKC + qrow) * 64;
#pragma unroll
                for (int nt = 0; nt < 2; nt++) {
                    int col = wn * 16 + nt * 8 + tig * 2;
                    __half2 w = __floats2half2_rn(acc[nt][half * 2] * iv,
                                                  acc[nt][half * 2 + 1] * iv);
                    *(__half2*)&g_attH[base + col] = w;
                }
            }
        }
        __syncthreads();
    }
}

// ======================= launch =======================
extern "C" void kernel_launch(void* const* d_in, const int* in_sizes, int n_in,
                              void* d_out, int out_size)
{
    const float* x        = (const float*)d_in[0];
    const float* question = (const float*)d_in[1];
    const float* Wq       = (const float*)d_in[2];
    const float* Wkv      = (const float*)d_in[3];
    const float* Wproj    = (const float*)d_in[4];
    const float* bproj    = (const float*)d_in[5];
    float* out = (float*)d_out;

    cudaFuncSetAttribute(fine_attn, cudaFuncAttributeMaxDynamicSharedMemorySize, FINE_SMEM);
    cudaFuncSetAttribute(gemm_tc<0>, cudaFuncAttributeMaxDynamicSharedMemorySize, GEMM_SMEM);
    cudaFuncSetAttribute(gemm_tc<1>, cudaFuncAttributeMaxDynamicSharedMemorySize, GEMM_SMEM);
    cudaFuncSetAttribute(gemm_tc<2>, cudaFuncAttributeMaxDynamicSharedMemorySize, GEMM_SMEM);

    // weight prep (one launch) + input fp16 converts
    transposeW<<<dim3(1536 / 32, 768 / 32, 3), 256>>>(Wq, Wkv, Wproj);
    {
        __half* qH; cudaGetSymbolAddress((void**)&qH, g_qH);
        __half* xH; cudaGetSymbolAddress((void**)&xH, g_xH);
        int gq = BB * NQ * (KDIM / 8);
        int gx = BB * NV * (KDIM / 8);
        convertH<<<(gq + 255) / 256, 256>>>(question, qH, gq, 0.125f);
        convertH<<<(gx + 255) / 256, 256>>>(x, xH, gx, 1.0f);
    }
    __half* qH; cudaGetSymbolAddress((void**)&qH, g_qH);
    __half* xH; cudaGetSymbolAddress((void**)&xH, g_xH);

    // q projection
    gemm_tc<0><<<dim3(768 / BN, (BB * NQ + BM - 1) / BM), 256, GEMM_SMEM>>>(
        qH, nullptr, nullptr, BB * NQ);

    // kv projection
    gemm_tc<1><<<dim3(1536 / BN, (BB * NV) / BM), 256, GEMM_SMEM>>>(
        xH, nullptr, nullptr, BB * NV);

    // attention
    cls_attn<<<BHN, 256>>>();
    fine_attn<<<BHN * FF, 512, FINE_SMEM>>>();

    // output projection
    gemm_tc<2><<<dim3(768 / BN, (BB * NOUT + BM - 1) / BM), 256, GEMM_SMEM>>>(
        nullptr, bproj, out, BB * NOUT);
}

// round 15
// speedup vs baseline: 1.3379x; 1.0596x over previous
#include <cuda_runtime.h>
#include <cuda_fp16.h>
#include <cstdint>
#include <math.h>

// Problem constants
#define BB    32
#define NQ    197
#define NV    1568
#define DIMD  768
#define HH    12
#define FF    8
#define NKC   196
#define NOUT  1569
#define BHN   384
#define KDIM  768

// ---------------- scratch (device globals) ----------------
__device__ float  g_q[(size_t)BHN * NQ * 64];
__device__ float  g_k[(size_t)BHN * NV * 64];
__device__ float  g_v[(size_t)BHN * NV * 64];
__device__ __half g_attH[(size_t)BHN * NOUT * 64];     // fp16, written by attention
__device__ __half g_qH[(size_t)BB * NQ * KDIM];        // question fp16, pre-scaled 0.125
__device__ __half g_xH[(size_t)BB * NV * KDIM];        // x fp16
__device__ __half g_wqTH[768 * 768];                   // W^T [N][K] fp16
__device__ __half g_wkvTH[1536 * 768];
__device__ __half g_wpTH[768 * 768];

// ======================= helpers =======================
__device__ __forceinline__ uint32_t smem_to_u32(const void* p) {
    uint32_t a;
    asm("{ .reg .u64 t; cvta.to.shared.u64 t, %1; cvt.u32.u64 %0, t; }" : "=r"(a) : "l"(p));
    return a;
}
__device__ __forceinline__ uint32_t to_tf32_rn(float x) {
    uint32_t r;
    asm("cvt.rn.tf32.f32 %0, %1;" : "=r"(r) : "f"(x));
    return r;
}
__device__ __forceinline__ float rnd_tf32(float x) { return __uint_as_float(to_tf32_rn(x)); }
__device__ __forceinline__ float4 f4_rnd(float4 v) {
    v.x = rnd_tf32(v.x); v.y = rnd_tf32(v.y); v.z = rnd_tf32(v.z); v.w = rnd_tf32(v.w);
    return v;
}
__device__ __forceinline__ void sts_pair8(float* dst, float4 v0, float4 v1) {
    *(float4*)dst       = make_float4(v0.x, v1.x, v0.y, v1.y);
    *(float4*)(dst + 4) = make_float4(v0.z, v1.z, v0.w, v1.w);
}
__device__ __forceinline__ void cp_async16(uint32_t smem_addr, const void* gptr) {
    asm volatile("cp.async.cg.shared.global [%0], [%1], 16;"
                 :: "r"(smem_addr), "l"(gptr));
}
__device__ __forceinline__ void cp_async16p(uint32_t smem_addr, const void* gptr, bool pred) {
    int sz = pred ? 16 : 0;
    asm volatile("cp.async.cg.shared.global [%0], [%1], 16, %2;"
                 :: "r"(smem_addr), "l"(gptr), "r"(sz));
}
#define CP_COMMIT() asm volatile("cp.async.commit_group;" ::: "memory")
#define CP_WAIT(n)  asm volatile("cp.async.wait_group %0;" :: "n"(n) : "memory")

// tf32 m16n8k8 (attention)
__device__ __forceinline__ void mma_tf32(float* c, const uint32_t* a, const uint32_t* b) {
    asm volatile(
        "mma.sync.aligned.m16n8k8.row.col.f32.tf32.tf32.f32 "
        "{%0,%1,%2,%3}, {%4,%5,%6,%7}, {%8,%9}, {%0,%1,%2,%3};"
        : "+f"(c[0]), "+f"(c[1]), "+f"(c[2]), "+f"(c[3])
        : "r"(a[0]), "r"(a[1]), "r"(a[2]), "r"(a[3]), "r"(b[0]), "r"(b[1]));
}
// fp16 m16n8k16 (projection GEMMs)
__device__ __forceinline__ void mma_f16(float* c, const uint32_t* a, const uint32_t* b) {
    asm volatile(
        "mma.sync.aligned.m16n8k16.row.col.f32.f16.f16.f32 "
        "{%0,%1,%2,%3}, {%4,%5,%6,%7}, {%8,%9}, {%0,%1,%2,%3};"
        : "+f"(c[0]), "+f"(c[1]), "+f"(c[2]), "+f"(c[3])
        : "r"(a[0]), "r"(a[1]), "r"(a[2]), "r"(a[3]), "r"(b[0]), "r"(b[1]));
}
__device__ __forceinline__ void ldmatrix_x4(uint32_t& r0, uint32_t& r1,
                                            uint32_t& r2, uint32_t& r3, uint32_t addr) {
    asm volatile("ldmatrix.sync.aligned.m8n8.x4.shared.b16 {%0,%1,%2,%3}, [%4];"
                 : "=r"(r0), "=r"(r1), "=r"(r2), "=r"(r3) : "r"(addr));
}

// FMA-pipe exp
__device__ __forceinline__ float fast_exp(float x) {
    x = fmaxf(x, -87.0f);
    float y = x * 1.4426950408889634f;
    float r = y + 12582912.0f;
    int   n = __float_as_int(r) - 0x4B400000;
    float f = y - (r - 12582912.0f);
    float p = 1.3333558146e-3f;
    p = fmaf(p, f, 9.6181291076e-3f);
    p = fmaf(p, f, 5.5504108664e-2f);
    p = fmaf(p, f, 2.4022650696e-1f);
    p = fmaf(p, f, 6.9314718056e-1f);
    p = fmaf(p, f, 1.0f);
    return __int_as_float(__float_as_int(p) + (n << 23));
}

// ======================= fp32 -> fp16 convert (+scale), 8 elems/thread =======================
__global__ __launch_bounds__(256)
void convertH(const float* __restrict__ src, __half* __restrict__ dst,
              int n8, float scale)
{
    int i = blockIdx.x * 256 + threadIdx.x;
    if (i >= n8) return;
    const float4* s = (const float4*)src + (size_t)i * 2;
    float4 v0 = s[0], v1 = s[1];
    __half2 h0 = __floats2half2_rn(v0.x * scale, v0.y * scale);
    __half2 h1 = __floats2half2_rn(v0.z * scale, v0.w * scale);
    __half2 h2 = __floats2half2_rn(v1.x * scale, v1.y * scale);
    __half2 h3 = __floats2half2_rn(v1.z * scale, v1.w * scale);
    uint4 o;
    o.x = *(uint32_t*)&h0; o.y = *(uint32_t*)&h1;
    o.z = *(uint32_t*)&h2; o.w = *(uint32_t*)&h3;
    ((uint4*)dst)[i] = o;
}

// ======================= weight transpose -> fp16 [N][K] (one launch, z selects) ==========
__global__ __launch_bounds__(256)
void transposeW(const float* __restrict__ Wq, const float* __restrict__ Wkv,
                const float* __restrict__ Wproj)
{
    const int which = blockIdx.z;
    const float* src = (which == 0) ? Wq : (which == 1) ? Wkv : Wproj;
    __half* dst = (which == 0) ? g_wqTH : (which == 1) ? g_wkvTH : g_wpTH;
    const int N = (which == 1) ? 1536 : 768;
    const int K = 768;

    int bx = blockIdx.x * 32;
    int by = blockIdx.y * 32;
    if (bx >= N) return;

    __shared__ float t[32][33];
    int txl = threadIdx.x & 31;
    int tyl = threadIdx.x >> 5;
#pragma unroll
    for (int j = 0; j < 32; j += 8)
        t[tyl + j][txl] = src[(size_t)(by + tyl + j) * N + bx + txl];
    __syncthreads();
#pragma unroll
    for (int j = 0; j < 32; j += 8)
        dst[(size_t)(bx + tyl + j) * K + by + txl] = __float2half(t[txl][tyl + j]);
}

// ======================= fp16 mma.sync GEMM: 3-stage ring, 1 sync/ktile, ldmatrix ==========
constexpr int BM = 128, BN = 128, BK = 32;      // BK in halfs (2 k16 steps)
constexpr int SK_H = 40;                         // halfs per row (stride 20 words: bank-clean)
constexpr int OP_HALFS = 128 * SK_H;             // 5120
constexpr int STAGE_HALFS = 2 * OP_HALFS;        // 10240 halfs = 20480 B
constexpr int GSTAGES = 3;
constexpr int GEMM_SMEM = GSTAGES * STAGE_HALFS * 2;   // 61440 bytes
constexpr int KT = KDIM / BK;                    // 24

template<int MODE>
__global__ __launch_bounds__(256, 2)
void gemm_tc(const __half* __restrict__ A, const float* __restrict__ bias,
             float* __restrict__ Cout, int M)
{
    extern __shared__ __half smh[];
    const uint32_t sb32 = smem_to_u32(smh);
    const int tid   = threadIdx.x;
    const int warp  = tid >> 5;
    const int lane  = tid & 31;
    const int group = lane >> 2;
    const int tig   = lane & 3;
    const int wm    = warp & 3;
    const int wn    = warp >> 2;
    const int row0  = blockIdx.y * BM;
    const int col0  = blockIdx.x * BN;

    const __half* BT = (MODE == 0) ? g_wqTH : (MODE == 1) ? g_wkvTH : g_wpTH;

    float acc[2][8][4];
#pragma unroll
    for (int mt = 0; mt < 2; mt++)
#pragma unroll
        for (int nt = 0; nt < 8; nt++)
#pragma unroll
            for (int c = 0; c < 4; c++) acc[mt][nt][c] = 0.f;

    // ldmatrix per-thread coordinates
    const int lm_m = lane >> 3;   // matrix id 0..3
    const int lm_i = lane & 7;    // row within 8x8
    const int a_row = wm * 32 + (lm_m & 1) * 8 + lm_i;   // + mt*16
    const int a_col = (lm_m >> 1) * 8;
    const int b_row = wn * 64 + (lm_m >> 1) * 8 + lm_i;  // + p*16
    const int b_col = (lm_m & 1) * 8;

    auto load_stage = [&](int kt, int s) {
        const uint32_t aoff = sb32 + (uint32_t)(s * STAGE_HALFS) * 2;
        const uint32_t boff = aoff + (uint32_t)OP_HALFS * 2;
        const int k0 = kt * BK;
#pragma unroll
        for (int it = 0; it < 2; it++) {
            int idx = tid + it * 256;
            int r = idx >> 2, ch = idx & 3;          // 128 rows x 4 16B-chunks
            int grow = row0 + r;
            bool ok = grow < M;
            int gr = ok ? grow : 0;
            const __half* src;
            if (MODE == 2) {
                int b_ = gr / NOUT;
                int n_ = gr - b_ * NOUT;
                int kk = k0 + ch * 8;
                int h = kk >> 6, dd = kk & 63;
                src = &g_attH[(((size_t)(b_ * HH + h) * NOUT + n_) << 6) + dd];
            } else {
                src = &A[(size_t)gr * KDIM + k0 + ch * 8];
            }
            cp_async16p(aoff + (uint32_t)(r * SK_H + ch * 8) * 2, src, ok);
        }
#pragma unroll
        for (int it = 0; it < 2; it++) {
            int idx = tid + it * 256;
            int r = idx >> 2, ch = idx & 3;
            cp_async16(boff + (uint32_t)(r * SK_H + ch * 8) * 2,
                       &BT[(size_t)(col0 + r) * KDIM + k0 + ch * 8]);
        }
        CP_COMMIT();
    };

    load_stage(0, 0);
    load_stage(1, 1);

    for (int kt = 0; kt < KT; kt++) {
        if (kt < KT - 1) { CP_WAIT(1); } else { CP_WAIT(0); }
        __syncthreads();
        // stage (kt+2)%3 == (kt-1)%3 was consumed before the sync above
        if (kt + 2 < KT) load_stage(kt + 2, (kt + 2) % GSTAGES);

        const uint32_t asb = sb32 + (uint32_t)((kt % GSTAGES) * STAGE_HALFS) * 2;
        const uint32_t bsb = asb + (uint32_t)OP_HALFS * 2;

#pragma unroll
        for (int s = 0; s < 2; s++) {
            const int kb = s * 16;
            uint32_t af[2][4];
#pragma unroll
            for (int mt = 0; mt < 2; mt++)
                ldmatrix_x4(af[mt][0], af[mt][1], af[mt][2], af[mt][3],
                            asb + (uint32_t)((a_row + mt * 16) * SK_H + kb + a_col) * 2);
#pragma unroll
            for (int p = 0; p < 4; p++) {
                uint32_t t0, t1, t2, t3;
                ldmatrix_x4(t0, t1, t2, t3,
                            bsb + (uint32_t)((b_row + p * 16) * SK_H + kb + b_col) * 2);
                uint32_t b0[2] = { t0, t1 };
                uint32_t b1[2] = { t2, t3 };
                mma_f16(acc[0][2 * p],     af[0], b0);
                mma_f16(acc[1][2 * p],     af[1], b0);
                mma_f16(acc[0][2 * p + 1], af[0], b1);
                mma_f16(acc[1][2 * p + 1], af[1], b1);
            }
        }
    }

    // ---- epilogue
#pragma unroll
    for (int mt = 0; mt < 2; mt++) {
#pragma unroll
        for (int half = 0; half < 2; half++) {
            int row = row0 + wm * 32 + mt * 16 + group + half * 8;
            if (row >= M) continue;
            int b_, n_;
            if (MODE == 0) { b_ = row / NQ;   n_ = row - b_ * NQ; }
            else if (MODE == 1) { b_ = row / NV; n_ = row - b_ * NV; }
            else { b_ = 0; n_ = 0; }
#pragma unroll
            for (int nt = 0; nt < 8; nt++) {
                int col = col0 + wn * 64 + nt * 8 + tig * 2;
                float v0 = acc[mt][nt][half * 2 + 0];
                float v1 = acc[mt][nt][half * 2 + 1];
                if (MODE == 0) {
                    int h = col >> 6, dd = col & 63;
                    *(float2*)&g_q[(((size_t)(b_ * HH + h) * NQ + n_) << 6) + dd] =
                        make_float2(v0, v1);    // 0.125 pre-folded into g_qH
                } else if (MODE == 1) {
                    float2 w = make_float2(v0, v1);
                    if (col < DIMD) {
                        int h = col >> 6, dd = col & 63;
                        *(float2*)&g_k[(((size_t)(b_ * HH + h) * NV + n_) << 6) + dd] = w;
                    } else {
                        int c2 = col - DIMD;
                        int h = c2 >> 6, dd = c2 & 63;
                        *(float2*)&g_v[(((size_t)(b_ * HH + h) * NV + n_) << 6) + dd] = w;
                    }
                } else {
                    float2 w = make_float2(v0 + bias[col], v1 + bias[col + 1]);
                    *(float2*)&Cout[(size_t)row * DIMD + col] = w;
                }
            }
        }
    }
}

// ======================= cls-token attention (writes fp16 g_attH) =======================
__global__ __launch_bounds__(256)
void cls_attn()
{
    __shared__ float qsh[64];
    __shared__ float ssh[NV];
    __shared__ float red[40];
    __shared__ float osh[4][64];

    const int bh   = blockIdx.x;
    const int tid  = threadIdx.x;
    const int lane = tid & 31;
    const int warp = tid >> 5;

    if (tid < 64) qsh[tid] = g_q[((size_t)bh * NQ) * 64 + tid];
    __syncthreads();

    for (int j = warp; j < NV; j += 8) {
        const float* kr = &g_k[((size_t)bh * NV + j) * 64];
        float p = qsh[lane] * kr[lane] + qsh[lane + 32] * kr[lane + 32];
#pragma unroll
        for (int o = 16; o > 0; o >>= 1) p += __shfl_xor_sync(0xffffffffu, p, o);
        if (lane == 0) ssh[j] = p;
    }
    __syncthreads();

    float m = -1e30f;
    for (int j = tid; j < NV; j += 256) m = fmaxf(m, ssh[j]);
#pragma unroll
    for (int o = 16; o > 0; o >>= 1) m = fmaxf(m, __shfl_xor_sync(0xffffffffu, m, o));
    if (lane == 0) red[warp] = m;
    __syncthreads();
    if (tid == 0) {
        float mm = red[0];
        for (int w = 1; w < 8; w++) mm = fmaxf(mm, red[w]);
        red[32] = mm;
    }
    __syncthreads();
    m = red[32];

    float s = 0.f;
    for (int j = tid; j < NV; j += 256) {
        float e = fast_exp(ssh[j] - m);
        ssh[j] = e;
        s += e;
    }
#pragma unroll
    for (int o = 16; o > 0; o >>= 1) s += __shfl_xor_sync(0xffffffffu, s, o);
    if (lane == 0) red[8 + warp] = s;
    __syncthreads();
    if (tid == 0) {
        float ss = 0.f;
        for (int w = 0; w < 8; w++) ss += red[8 + w];
        red[33] = 1.f / ss;
    }
    __syncthreads();
    const float inv = red[33];

    const int g = tid >> 6, dd = tid & 63;
    float o = 0.f;
    for (int j = g; j < NV; j += 4)
        o = fmaf(ssh[j], g_v[((size_t)bh * NV + j) * 64 + dd], o);
    osh[g][dd] = o;
    __syncthreads();
    if (tid < 64) {
        float r = (osh[0][tid] + osh[1][tid] + osh[2][tid] + osh[3][tid]) * inv;
        g_attH[((size_t)bh * NOUT) * 64 + tid] = __float2half(r);
    }
}

// ======================= fine attention — R14 version (unchanged) ===========
constexpr int QWN = 68;
constexpr int KW  = 72;
constexpr int VWN = 72;
constexpr int SW  = 228;
constexpr int Q0_OFF = 0;
constexpr int Q1_OFF = Q0_OFF + 64 * QWN;
constexpr int K_OFF  = Q1_OFF + 64 * QWN;
constexpr int V_OFF  = K_OFF + 224 * KW;
constexpr int S_OFF  = V_OFF + 200 * VWN;
constexpr int I_OFF  = S_OFF + 64 * SW;
constexpr int FINE_SMEM = (I_OFF + 64) * 4;

__global__ __launch_bounds__(512, 1)
void fine_attn()
{
    extern __shared__ float smf[];
    float* Ks = smf + K_OFF;
    float* Vn = smf + V_OFF;
    float* Ss = smf + S_OFF;
    float* Iv = smf + I_OFF;

    const int bh    = blockIdx.x >> 3;
    const int f     = blockIdx.x & 7;
    const int tid   = threadIdx.x;
    const int warp  = tid >> 5;
    const int lane  = tid & 31;
    const int group = lane >> 2;
    const int tig   = lane & 3;
    const int wm    = warp & 3;
    const int wn    = warp >> 2;

    const uint32_t sb32 = smem_to_u32(smf);
    const float* kg = &g_k[((size_t)bh * NV + (size_t)f * NKC) * 64];
    const float* vg = &g_v[((size_t)bh * NV + (size_t)f * NKC) * 64];
    const float* qg = &g_q[((size_t)bh * NQ + 1) * 64];

    for (int idx = tid; idx < NKC * 16; idx += 512) {
        int j = idx >> 4, c4 = (idx & 15) << 2;
        cp_async16(sb32 + (uint32_t)(V_OFF + j * VWN + c4) * 4, &vg[j * 64 + c4]);
    }
    CP_COMMIT();

    auto loadQ = [&](int qc, int buf) {
        const int rows = (qc == 3) ? (NKC - 192) : 64;
        const uint32_t qoff = sb32 + (uint32_t)((buf ? Q1_OFF : Q0_OFF)) * 4;
#pragma unroll
        for (int it = 0; it < 2; it++) {
            int idx = tid + it * 512;
            int r = idx >> 4, c4 = (idx & 15) << 2;
            cp_async16p(qoff + (uint32_t)(r * QWN + c4) * 4,
                        &qg[(size_t)(qc * 64 + r) * 64 + c4], r < rows);
        }
        CP_COMMIT();
    };
    loadQ(0, 0);

    for (int u = tid; u < 224 * 8; u += 512) {
        int r = u >> 3, g = u & 7;
        float4 v0 = make_float4(0.f, 0.f, 0.f, 0.f), v1 = v0;
        if (r < NKC) {
            v0 = f4_rnd(*(const float4*)&kg[r * 64 + g * 8]);
            v1 = f4_rnd(*(const float4*)&kg[r * 64 + g * 8 + 4]);
        }
        sts_pair8(&Ks[r * KW + g * 8], v0, v1);
    }
    for (int idx = tid; idx < 4 * 18; idx += 512) {
        int r = 196 + idx / 18, c4 = (idx % 18) * 4;
        *(float4*)&Vn[r * VWN + c4] = make_float4(0.f, 0.f, 0.f, 0.f);
    }

    for (int qc = 0; qc < 4; qc++) {
        if (qc < 3) loadQ(qc + 1, (qc + 1) & 1);
        if (qc < 3) { CP_WAIT(1); } else { CP_WAIT(0); }
        __syncthreads();

        const float* Qc = smf + ((qc & 1) ? Q1_OFF : Q0_OFF);

        // ---- S = Q @ K^T
        {
            float acc[7][4];
#pragma unroll
            for (int nt = 0; nt < 7; nt++)
#pragma unroll
                for (int c = 0; c < 4; c++) acc[nt][c] = 0.f;

#pragma unroll
            for (int ks = 0; ks < 8; ks++) {
                const int kc = ks * 8 + tig;
                const int ko = ks * 8 + 2 * tig;
                const int r = wm * 16 + group;
                uint32_t af[4];
                af[0] = to_tf32_rn(Qc[r * QWN + kc]);
                af[1] = to_tf32_rn(Qc[(r + 8) * QWN + kc]);
                af[2] = to_tf32_rn(Qc[r * QWN + kc + 4]);
                af[3] = to_tf32_rn(Qc[(r + 8) * QWN + kc + 4]);
#pragma unroll
                for (int nt = 0; nt < 7; nt++) {
                    int n = wn * 56 + nt * 8 + group;
                    float2 b = *(const float2*)&Ks[n * KW + ko];
                    uint32_t bf[2] = { __float_as_uint(b.x), __float_as_uint(b.y) };
                    mma_tf32(acc[nt], af, bf);
                }
            }
            const int r = wm * 16 + group;
#pragma unroll
            for (int nt = 0; nt < 7; nt++) {
                int n = wn * 56 + nt * 8 + tig * 2;
                *(float2*)&Ss[r * SW + n]       = make_float2(acc[nt][0], acc[nt][1]);
                *(float2*)&Ss[(r + 8) * SW + n] = make_float2(acc[nt][2], acc[nt][3]);
            }
        }
        __syncthreads();

        // ---- softmax
        {
            float mx[4], sum[4];
#pragma unroll
            for (int rr = 0; rr < 4; rr++) mx[rr] = -1e30f;
#pragma unroll
            for (int it = 0; it < 7; it++) {
                int j = lane + it * 32;
                if (j < NKC) {
#pragma unroll
                    for (int rr = 0; rr < 4; rr++)
                        mx[rr] = fmaxf(mx[rr], Ss[(warp * 4 + rr) * SW + j]);
                }
            }
#pragma unroll
            for (int o = 16; o > 0; o >>= 1)
#pragma unroll
                for (int rr = 0; rr < 4; rr++)
                    mx[rr] = fmaxf(mx[rr], __shfl_xor_sync(0xffffffffu, mx[rr], o));
#pragma unroll
            for (int rr = 0; rr < 4; rr++) sum[rr] = 0.f;
#pragma unroll
            for (int it = 0; it < 7; it++) {
                int j = lane + it * 32;
                if (j < NKC) {
#pragma unroll
                    for (int rr = 0; rr < 4; rr++) {
                        float* sp = &Ss[(warp * 4 + rr) * SW + j];
                        float e = fast_exp(*sp - mx[rr]);
                        *sp = rnd_tf32(e);
                        sum[rr] += e;
                    }
                }
            }
#pragma unroll
            for (int o = 16; o > 0; o >>= 1)
#pragma unroll
                for (int rr = 0; rr < 4; rr++)
                    sum[rr] += __shfl_xor_sync(0xffffffffu, sum[rr], o);
            if (lane == 0) {
#pragma unroll
                for (int rr = 0; rr < 4; rr++) Iv[warp * 4 + rr] = 1.f / sum[rr];
            }
        }
        __syncthreads();

        // ---- O = P @ V
        {
            float acc[2][4];
#pragma unroll
            for (int nt = 0; nt < 2; nt++)
#pragma unroll
                for (int c = 0; c < 4; c++) acc[nt][c] = 0.f;

            for (int ks = 0; ks < 25; ks++) {
                const int kc = ks * 8 + tig;
                const int r = wm * 16 + group;
                uint32_t af[4] = {
                    __float_as_uint(Ss[r * SW + kc]),
                    __float_as_uint(Ss[(r + 8) * SW + kc]),
                    __float_as_uint(Ss[r * SW + kc + 4]),
                    __float_as_uint(Ss[(r + 8) * SW + kc + 4]) };
#pragma unroll
                for (int nt = 0; nt < 2; nt++) {
                    int n = wn * 16 + nt * 8 + group;
                    uint32_t bf[2];
                    bf[0] = to_tf32_rn(Vn[(ks * 8 + tig) * VWN + n]);
                    bf[1] = to_tf32_rn(Vn[(ks * 8 + tig + 4) * VWN + n]);
                    mma_tf32(acc[nt], af, bf);
                }
            }
#pragma unroll
            for (int half = 0; half < 2; half++) {
                int rl = wm * 16 + group + half * 8;
                int qrow = qc * 64 + rl;
                if (qrow >= NKC) continue;
                float iv = Iv[rl];
                size_t base = ((size_t)bh * NOUT + 1 + (size_t)f * NKC + qrow) * 64;
#pragma unroll
                for (int nt = 0; nt < 2; nt++) {
                    int col = wn * 16 + nt * 8 + tig * 2;
                    __half2 w = __floats2half2_rn(acc[nt][half * 2] * iv,
                                                  acc[nt][half * 2 + 1] * iv);
                    *(__half2*)&g_attH[base + col] = w;
                }
            }
        }
        __syncthreads();
    }
}

// ======================= launch =======================
extern "C" void kernel_launch(void* const* d_in, const int* in_sizes, int n_in,
                              void* d_out, int out_size)
{
    const float* x        = (const float*)d_in[0];
    const float* question = (const float*)d_in[1];
    const float* Wq       = (const float*)d_in[2];
    const float* Wkv      = (const float*)d_in[3];
    const float* Wproj    = (const float*)d_in[4];
    const float* bproj    = (const float*)d_in[5];
    float* out = (float*)d_out;

    cudaFuncSetAttribute(fine_attn, cudaFuncAttributeMaxDynamicSharedMemorySize, FINE_SMEM);
    cudaFuncSetAttribute(gemm_tc<0>, cudaFuncAttributeMaxDynamicSharedMemorySize, GEMM_SMEM);
    cudaFuncSetAttribute(gemm_tc<1>, cudaFuncAttributeMaxDynamicSharedMemorySize, GEMM_SMEM);
    cudaFuncSetAttribute(gemm_tc<2>, cudaFuncAttributeMaxDynamicSharedMemorySize, GEMM_SMEM);

    // weight prep (one launch) + input fp16 converts
    transposeW<<<dim3(1536 / 32, 768 / 32, 3), 256>>>(Wq, Wkv, Wproj);
    {
        __half* qH; cudaGetSymbolAddress((void**)&qH, g_qH);
        __half* xH; cudaGetSymbolAddress((void**)&xH, g_xH);
        int gq = BB * NQ * (KDIM / 8);
        int gx = BB * NV * (KDIM / 8);
        convertH<<<(gq + 255) / 256, 256>>>(question, qH, gq, 0.125f);
        convertH<<<(gx + 255) / 256, 256>>>(x, xH, gx, 1.0f);
    }
    __half* qH; cudaGetSymbolAddress((void**)&qH, g_qH);
    __half* xH; cudaGetSymbolAddress((void**)&xH, g_xH);

    // q projection
    gemm_tc<0><<<dim3(768 / BN, (BB * NQ + BM - 1) / BM), 256, GEMM_SMEM>>>(
        qH, nullptr, nullptr, BB * NQ);

    // kv projection
    gemm_tc<1><<<dim3(1536 / BN, (BB * NV) / BM), 256, GEMM_SMEM>>>(
        xH, nullptr, nullptr, BB * NV);

    // attention
    cls_attn<<<BHN, 256>>>();
    fine_attn<<<BHN * FF, 512, FINE_SMEM>>>();

    // output projection
    gemm_tc<2><<<dim3(768 / BN, (BB * NOUT + BM - 1) / BM), 256, GEMM_SMEM>>>(
        nullptr, bproj, out, BB * NOUT);
}

// round 16
// speedup vs baseline: 1.4024x; 1.0483x over previous
#include <cuda_runtime.h>
#include <cuda_fp16.h>
#include <cstdint>
#include <math.h>

// Problem constants
#define BB    32
#define NQ    197
#define NV    1568
#define DIMD  768
#define HH    12
#define FF    8
#define NKC   196
#define NOUT  1569
#define BHN   384
#define KDIM  768

// ---------------- scratch (device globals) ----------------
__device__ float  g_q[(size_t)BHN * NQ * 64];
__device__ float  g_k[(size_t)BHN * NV * 64];
__device__ float  g_v[(size_t)BHN * NV * 64];
__device__ __half g_attH[(size_t)BHN * NOUT * 64];     // fp16, written by attention
__device__ __half g_qH[(size_t)BB * NQ * KDIM];        // question fp16, pre-scaled 0.125
__device__ __half g_xH[(size_t)BB * NV * KDIM];        // x fp16
__device__ __half g_wqTH[768 * 768];                   // W^T [N][K] fp16
__device__ __half g_wkvTH[1536 * 768];
__device__ __half g_wpTH[768 * 768];

// ======================= helpers =======================
__device__ __forceinline__ uint32_t smem_to_u32(const void* p) {
    uint32_t a;
    asm("{ .reg .u64 t; cvta.to.shared.u64 t, %1; cvt.u32.u64 %0, t; }" : "=r"(a) : "l"(p));
    return a;
}
__device__ __forceinline__ uint32_t to_tf32_rn(float x) {
    uint32_t r;
    asm("cvt.rn.tf32.f32 %0, %1;" : "=r"(r) : "f"(x));
    return r;
}
__device__ __forceinline__ float rnd_tf32(float x) { return __uint_as_float(to_tf32_rn(x)); }
__device__ __forceinline__ float4 f4_rnd(float4 v) {
    v.x = rnd_tf32(v.x); v.y = rnd_tf32(v.y); v.z = rnd_tf32(v.z); v.w = rnd_tf32(v.w);
    return v;
}
__device__ __forceinline__ void sts_pair8(float* dst, float4 v0, float4 v1) {
    *(float4*)dst       = make_float4(v0.x, v1.x, v0.y, v1.y);
    *(float4*)(dst + 4) = make_float4(v0.z, v1.z, v0.w, v1.w);
}
__device__ __forceinline__ void cp_async16(uint32_t smem_addr, const void* gptr) {
    asm volatile("cp.async.cg.shared.global [%0], [%1], 16;"
                 :: "r"(smem_addr), "l"(gptr));
}
__device__ __forceinline__ void cp_async16p(uint32_t smem_addr, const void* gptr, bool pred) {
    int sz = pred ? 16 : 0;
    asm volatile("cp.async.cg.shared.global [%0], [%1], 16, %2;"
                 :: "r"(smem_addr), "l"(gptr), "r"(sz));
}
#define CP_COMMIT() asm volatile("cp.async.commit_group;" ::: "memory")
#define CP_WAIT(n)  asm volatile("cp.async.wait_group %0;" :: "n"(n) : "memory")

// tf32 m16n8k8 (attention)
__device__ __forceinline__ void mma_tf32(float* c, const uint32_t* a, const uint32_t* b) {
    asm volatile(
        "mma.sync.aligned.m16n8k8.row.col.f32.tf32.tf32.f32 "
        "{%0,%1,%2,%3}, {%4,%5,%6,%7}, {%8,%9}, {%0,%1,%2,%3};"
        : "+f"(c[0]), "+f"(c[1]), "+f"(c[2]), "+f"(c[3])
        : "r"(a[0]), "r"(a[1]), "r"(a[2]), "r"(a[3]), "r"(b[0]), "r"(b[1]));
}
// fp16 m16n8k16 (projection GEMMs)
__device__ __forceinline__ void mma_f16(float* c, const uint32_t* a, const uint32_t* b) {
    asm volatile(
        "mma.sync.aligned.m16n8k16.row.col.f32.f16.f16.f32 "
        "{%0,%1,%2,%3}, {%4,%5,%6,%7}, {%8,%9}, {%0,%1,%2,%3};"
        : "+f"(c[0]), "+f"(c[1]), "+f"(c[2]), "+f"(c[3])
        : "r"(a[0]), "r"(a[1]), "r"(a[2]), "r"(a[3]), "r"(b[0]), "r"(b[1]));
}
__device__ __forceinline__ void ldmatrix_x4(uint32_t& r0, uint32_t& r1,
                                            uint32_t& r2, uint32_t& r3, uint32_t addr) {
    asm volatile("ldmatrix.sync.aligned.m8n8.x4.shared.b16 {%0,%1,%2,%3}, [%4];"
                 : "=r"(r0), "=r"(r1), "=r"(r2), "=r"(r3) : "r"(addr));
}

// FMA-pipe exp
__device__ __forceinline__ float fast_exp(float x) {
    x = fmaxf(x, -87.0f);
    float y = x * 1.4426950408889634f;
    float r = y + 12582912.0f;
    int   n = __float_as_int(r) - 0x4B400000;
    float f = y - (r - 12582912.0f);
    float p = 1.3333558146e-3f;
    p = fmaf(p, f, 9.6181291076e-3f);
    p = fmaf(p, f, 5.5504108664e-2f);
    p = fmaf(p, f, 2.4022650696e-1f);
    p = fmaf(p, f, 6.9314718056e-1f);
    p = fmaf(p, f, 1.0f);
    return __int_as_float(__float_as_int(p) + (n << 23));
}

// ======================= fp32 -> fp16 convert (+scale), 8 elems/thread =======================
__global__ __launch_bounds__(256)
void convertH(const float* __restrict__ src, __half* __restrict__ dst,
              int n8, float scale)
{
    int i = blockIdx.x * 256 + threadIdx.x;
    if (i >= n8) return;
    const float4* s = (const float4*)src + (size_t)i * 2;
    float4 v0 = s[0], v1 = s[1];
    __half2 h0 = __floats2half2_rn(v0.x * scale, v0.y * scale);
    __half2 h1 = __floats2half2_rn(v0.z * scale, v0.w * scale);
    __half2 h2 = __floats2half2_rn(v1.x * scale, v1.y * scale);
    __half2 h3 = __floats2half2_rn(v1.z * scale, v1.w * scale);
    uint4 o;
    o.x = *(uint32_t*)&h0; o.y = *(uint32_t*)&h1;
    o.z = *(uint32_t*)&h2; o.w = *(uint32_t*)&h3;
    ((uint4*)dst)[i] = o;
}

// ======================= weight transpose -> fp16 [N][K] (one launch, z selects) ==========
__global__ __launch_bounds__(256)
void transposeW(const float* __restrict__ Wq, const float* __restrict__ Wkv,
                const float* __restrict__ Wproj)
{
    const int which = blockIdx.z;
    const float* src = (which == 0) ? Wq : (which == 1) ? Wkv : Wproj;
    __half* dst = (which == 0) ? g_wqTH : (which == 1) ? g_wkvTH : g_wpTH;
    const int N = (which == 1) ? 1536 : 768;
    const int K = 768;

    int bx = blockIdx.x * 32;
    int by = blockIdx.y * 32;
    if (bx >= N) return;

    __shared__ float t[32][33];
    int txl = threadIdx.x & 31;
    int tyl = threadIdx.x >> 5;
#pragma unroll
    for (int j = 0; j < 32; j += 8)
        t[tyl + j][txl] = src[(size_t)(by + tyl + j) * N + bx + txl];
    __syncthreads();
#pragma unroll
    for (int j = 0; j < 32; j += 8)
        dst[(size_t)(bx + tyl + j) * K + by + txl] = __float2half(t[txl][tyl + j]);
}

// ======================= fp16 mma.sync GEMM: BK=64, 3-stage ring, 1 sync/ktile, ldmatrix ====
constexpr int BM = 128, BN = 128, BK = 64;      // BK in halfs (4 k16 steps)
constexpr int SK_H = 72;                         // halfs per row (144 B; 144%128=16 -> ldmatrix clean)
constexpr int OP_HALFS = 128 * SK_H;             // 9216
constexpr int STAGE_HALFS = 2 * OP_HALFS;        // 18432 halfs = 36864 B
constexpr int GSTAGES = 3;
constexpr int GEMM_SMEM = GSTAGES * STAGE_HALFS * 2;   // 110592 bytes
constexpr int KT = KDIM / BK;                    // 12

template<int MODE>
__global__ __launch_bounds__(256, 2)
void gemm_tc(const __half* __restrict__ A, const float* __restrict__ bias,
             float* __restrict__ Cout, int M)
{
    extern __shared__ __half smh[];
    const uint32_t sb32 = smem_to_u32(smh);
    const int tid   = threadIdx.x;
    const int warp  = tid >> 5;
    const int lane  = tid & 31;
    const int group = lane >> 2;
    const int tig   = lane & 3;
    const int wm    = warp & 3;
    const int wn    = warp >> 2;
    const int row0  = blockIdx.y * BM;
    const int col0  = blockIdx.x * BN;

    const __half* BT = (MODE == 0) ? g_wqTH : (MODE == 1) ? g_wkvTH : g_wpTH;

    float acc[2][8][4];
#pragma unroll
    for (int mt = 0; mt < 2; mt++)
#pragma unroll
        for (int nt = 0; nt < 8; nt++)
#pragma unroll
            for (int c = 0; c < 4; c++) acc[mt][nt][c] = 0.f;

    // ldmatrix per-thread coordinates
    const int lm_m = lane >> 3;   // matrix id 0..3
    const int lm_i = lane & 7;    // row within 8x8
    const int a_row = wm * 32 + (lm_m & 1) * 8 + lm_i;   // + mt*16
    const int a_col = (lm_m >> 1) * 8;
    const int b_row = wn * 64 + (lm_m >> 1) * 8 + lm_i;  // + p*16
    const int b_col = (lm_m & 1) * 8;

    // cp.async: 128 rows x 8 chunks(16B) per operand = 1024 chunks -> 4/thread/operand
    auto load_stage = [&](int kt, int s) {
        const uint32_t aoff = sb32 + (uint32_t)(s * STAGE_HALFS) * 2;
        const uint32_t boff = aoff + (uint32_t)OP_HALFS * 2;
        const int k0 = kt * BK;
#pragma unroll
        for (int it = 0; it < 4; it++) {
            int idx = tid + it * 256;
            int r = idx >> 3, ch = idx & 7;
            int grow = row0 + r;
            bool ok = grow < M;
            int gr = ok ? grow : 0;
            const __half* src;
            if (MODE == 2) {
                int b_ = gr / NOUT;
                int n_ = gr - b_ * NOUT;
                int kk = k0 + ch * 8;
                int h = kk >> 6, dd = kk & 63;
                src = &g_attH[(((size_t)(b_ * HH + h) * NOUT + n_) << 6) + dd];
            } else {
                src = &A[(size_t)gr * KDIM + k0 + ch * 8];
            }
            cp_async16p(aoff + (uint32_t)(r * SK_H + ch * 8) * 2, src, ok);
        }
#pragma unroll
        for (int it = 0; it < 4; it++) {
            int idx = tid + it * 256;
            int r = idx >> 3, ch = idx & 7;
            cp_async16(boff + (uint32_t)(r * SK_H + ch * 8) * 2,
                       &BT[(size_t)(col0 + r) * KDIM + k0 + ch * 8]);
        }
        CP_COMMIT();
    };

    load_stage(0, 0);
    load_stage(1, 1);

    for (int kt = 0; kt < KT; kt++) {
        if (kt < KT - 1) { CP_WAIT(1); } else { CP_WAIT(0); }
        __syncthreads();
        // stage (kt+2)%3 == (kt-1)%3 was consumed before the sync above
        if (kt + 2 < KT) load_stage(kt + 2, (kt + 2) % GSTAGES);

        const uint32_t asb = sb32 + (uint32_t)((kt % GSTAGES) * STAGE_HALFS) * 2;
        const uint32_t bsb = asb + (uint32_t)OP_HALFS * 2;

#pragma unroll
        for (int s = 0; s < 4; s++) {
            const int kb = s * 16;
            uint32_t af[2][4];
#pragma unroll
            for (int mt = 0; mt < 2; mt++)
                ldmatrix_x4(af[mt][0], af[mt][1], af[mt][2], af[mt][3],
                            asb + (uint32_t)((a_row + mt * 16) * SK_H + kb + a_col) * 2);
#pragma unroll
            for (int p = 0; p < 4; p++) {
                uint32_t t0, t1, t2, t3;
                ldmatrix_x4(t0, t1, t2, t3,
                            bsb + (uint32_t)((b_row + p * 16) * SK_H + kb + b_col) * 2);
                uint32_t b0[2] = { t0, t1 };
                uint32_t b1[2] = { t2, t3 };
                mma_f16(acc[0][2 * p],     af[0], b0);
                mma_f16(acc[1][2 * p],     af[1], b0);
                mma_f16(acc[0][2 * p + 1], af[0], b1);
                mma_f16(acc[1][2 * p + 1], af[1], b1);
            }
        }
    }

    // ---- epilogue
#pragma unroll
    for (int mt = 0; mt < 2; mt++) {
#pragma unroll
        for (int half = 0; half < 2; half++) {
            int row = row0 + wm * 32 + mt * 16 + group + half * 8;
            if (row >= M) continue;
            int b_, n_;
            if (MODE == 0) { b_ = row / NQ;   n_ = row - b_ * NQ; }
            else if (MODE == 1) { b_ = row / NV; n_ = row - b_ * NV; }
            else { b_ = 0; n_ = 0; }
#pragma unroll
            for (int nt = 0; nt < 8; nt++) {
                int col = col0 + wn * 64 + nt * 8 + tig * 2;
                float v0 = acc[mt][nt][half * 2 + 0];
                float v1 = acc[mt][nt][half * 2 + 1];
                if (MODE == 0) {
                    int h = col >> 6, dd = col & 63;
                    *(float2*)&g_q[(((size_t)(b_ * HH + h) * NQ + n_) << 6) + dd] =
                        make_float2(v0, v1);    // 0.125 pre-folded into g_qH
                } else if (MODE == 1) {
                    float2 w = make_float2(v0, v1);
                    if (col < DIMD) {
                        int h = col >> 6, dd = col & 63;
                        *(float2*)&g_k[(((size_t)(b_ * HH + h) * NV + n_) << 6) + dd] = w;
                    } else {
                        int c2 = col - DIMD;
                        int h = c2 >> 6, dd = c2 & 63;
                        *(float2*)&g_v[(((size_t)(b_ * HH + h) * NV + n_) << 6) + dd] = w;
                    }
                } else {
                    float2 w = make_float2(v0 + bias[col], v1 + bias[col + 1]);
                    *(float2*)&Cout[(size_t)row * DIMD + col] = w;
                }
            }
        }
    }
}

// ======================= cls-token attention (writes fp16 g_attH) =======================
__global__ __launch_bounds__(256)
void cls_attn()
{
    __shared__ float qsh[64];
    __shared__ float ssh[NV];
    __shared__ float red[40];
    __shared__ float osh[4][64];

    const int bh   = blockIdx.x;
    const int tid  = threadIdx.x;
    const int lane = tid & 31;
    const int warp = tid >> 5;

    if (tid < 64) qsh[tid] = g_q[((size_t)bh * NQ) * 64 + tid];
    __syncthreads();

    for (int j = warp; j < NV; j += 8) {
        const float* kr = &g_k[((size_t)bh * NV + j) * 64];
        float p = qsh[lane] * kr[lane] + qsh[lane + 32] * kr[lane + 32];
#pragma unroll
        for (int o = 16; o > 0; o >>= 1) p += __shfl_xor_sync(0xffffffffu, p, o);
        if (lane == 0) ssh[j] = p;
    }
    __syncthreads();

    float m = -1e30f;
    for (int j = tid; j < NV; j += 256) m = fmaxf(m, ssh[j]);
#pragma unroll
    for (int o = 16; o > 0; o >>= 1) m = fmaxf(m, __shfl_xor_sync(0xffffffffu, m, o));
    if (lane == 0) red[warp] = m;
    __syncthreads();
    if (tid == 0) {
        float mm = red[0];
        for (int w = 1; w < 8; w++) mm = fmaxf(mm, red[w]);
        red[32] = mm;
    }
    __syncthreads();
    m = red[32];

    float s = 0.f;
    for (int j = tid; j < NV; j += 256) {
        float e = fast_exp(ssh[j] - m);
        ssh[j] = e;
        s += e;
    }
#pragma unroll
    for (int o = 16; o > 0; o >>= 1) s += __shfl_xor_sync(0xffffffffu, s, o);
    if (lane == 0) red[8 + warp] = s;
    __syncthreads();
    if (tid == 0) {
        float ss = 0.f;
        for (int w = 0; w < 8; w++) ss += red[8 + w];
        red[33] = 1.f / ss;
    }
    __syncthreads();
    const float inv = red[33];

    const int g = tid >> 6, dd = tid & 63;
    float o = 0.f;
    for (int j = g; j < NV; j += 4)
        o = fmaf(ssh[j], g_v[((size_t)bh * NV + j) * 64 + dd], o);
    osh[g][dd] = o;
    __syncthreads();
    if (tid < 64) {
        float r = (osh[0][tid] + osh[1][tid] + osh[2][tid] + osh[3][tid]) * inv;
        g_attH[((size_t)bh * NOUT) * 64 + tid] = __float2half(r);
    }
}

// ======================= fine attention — R14/R15 version (unchanged) ===========
constexpr int QWN = 68;
constexpr int KW  = 72;
constexpr int VWN = 72;
constexpr int SW  = 228;
constexpr int Q0_OFF = 0;
constexpr int Q1_OFF = Q0_OFF + 64 * QWN;
constexpr int K_OFF  = Q1_OFF + 64 * QWN;
constexpr int V_OFF  = K_OFF + 224 * KW;
constexpr int S_OFF  = V_OFF + 200 * VWN;
constexpr int I_OFF  = S_OFF + 64 * SW;
constexpr int FINE_SMEM = (I_OFF + 64) * 4;

__global__ __launch_bounds__(512, 1)
void fine_attn()
{
    extern __shared__ float smf[];
    float* Ks = smf + K_OFF;
    float* Vn = smf + V_OFF;
    float* Ss = smf + S_OFF;
    float* Iv = smf + I_OFF;

    const int bh    = blockIdx.x >> 3;
    const int f     = blockIdx.x & 7;
    const int tid   = threadIdx.x;
    const int warp  = tid >> 5;
    const int lane  = tid & 31;
    const int group = lane >> 2;
    const int tig   = lane & 3;
    const int wm    = warp & 3;
    const int wn    = warp >> 2;

    const uint32_t sb32 = smem_to_u32(smf);
    const float* kg = &g_k[((size_t)bh * NV + (size_t)f * NKC) * 64];
    const float* vg = &g_v[((size_t)bh * NV + (size_t)f * NKC) * 64];
    const float* qg = &g_q[((size_t)bh * NQ + 1) * 64];

    for (int idx = tid; idx < NKC * 16; idx += 512) {
        int j = idx >> 4, c4 = (idx & 15) << 2;
        cp_async16(sb32 + (uint32_t)(V_OFF + j * VWN + c4) * 4, &vg[j * 64 + c4]);
    }
    CP_COMMIT();

    auto loadQ = [&](int qc, int buf) {
        const int rows = (qc == 3) ? (NKC - 192) : 64;
        const uint32_t qoff = sb32 + (uint32_t)((buf ? Q1_OFF : Q0_OFF)) * 4;
#pragma unroll
        for (int it = 0; it < 2; it++) {
            int idx = tid + it * 512;
            int r = idx >> 4, c4 = (idx & 15) << 2;
            cp_async16p(qoff + (uint32_t)(r * QWN + c4) * 4,
                        &qg[(size_t)(qc * 64 + r) * 64 + c4], r < rows);
        }
        CP_COMMIT();
    };
    loadQ(0, 0);

    for (int u = tid; u < 224 * 8; u += 512) {
        int r = u >> 3, g = u & 7;
        float4 v0 = make_float4(0.f, 0.f, 0.f, 0.f), v1 = v0;
        if (r < NKC) {
            v0 = f4_rnd(*(const float4*)&kg[r * 64 + g * 8]);
            v1 = f4_rnd(*(const float4*)&kg[r * 64 + g * 8 + 4]);
        }
        sts_pair8(&Ks[r * KW + g * 8], v0, v1);
    }
    for (int idx = tid; idx < 4 * 18; idx += 512) {
        int r = 196 + idx / 18, c4 = (idx % 18) * 4;
        *(float4*)&Vn[r * VWN + c4] = make_float4(0.f, 0.f, 0.f, 0.f);
    }

    for (int qc = 0; qc < 4; qc++) {
        if (qc < 3) loadQ(qc + 1, (qc + 1) & 1);
        if (qc < 3) { CP_WAIT(1); } else { CP_WAIT(0); }
        __syncthreads();

        const float* Qc = smf + ((qc & 1) ? Q1_OFF : Q0_OFF);

        // ---- S = Q @ K^T
        {
            float acc[7][4];
#pragma unroll
            for (int nt = 0; nt < 7; nt++)
#pragma unroll
                for (int c = 0; c < 4; c++) acc[nt][c] = 0.f;

#pragma unroll
            for (int ks = 0; ks < 8; ks++) {
                const int kc = ks * 8 + tig;
                const int ko = ks * 8 + 2 * tig;
                const int r = wm * 16 + group;
                uint32_t af[4];
                af[0] = to_tf32_rn(Qc[r * QWN + kc]);
                af[1] = to_tf32_rn(Qc[(r + 8) * QWN + kc]);
                af[2] = to_tf32_rn(Qc[r * QWN + kc + 4]);
                af[3] = to_tf32_rn(Qc[(r + 8) * QWN + kc + 4]);
#pragma unroll
                for (int nt = 0; nt < 7; nt++) {
                    int n = wn * 56 + nt * 8 + group;
                    float2 b = *(const float2*)&Ks[n * KW + ko];
                    uint32_t bf[2] = { __float_as_uint(b.x), __float_as_uint(b.y) };
                    mma_tf32(acc[nt], af, bf);
                }
            }
            const int r = wm * 16 + group;
#pragma unroll
            for (int nt = 0; nt < 7; nt++) {
                int n = wn * 56 + nt * 8 + tig * 2;
                *(float2*)&Ss[r * SW + n]       = make_float2(acc[nt][0], acc[nt][1]);
                *(float2*)&Ss[(r + 8) * SW + n] = make_float2(acc[nt][2], acc[nt][3]);
            }
        }
        __syncthreads();

        // ---- softmax
        {
            float mx[4], sum[4];
#pragma unroll
            for (int rr = 0; rr < 4; rr++) mx[rr] = -1e30f;
#pragma unroll
            for (int it = 0; it < 7; it++) {
                int j = lane + it * 32;
                if (j < NKC) {
#pragma unroll
                    for (int rr = 0; rr < 4; rr++)
                        mx[rr] = fmaxf(mx[rr], Ss[(warp * 4 + rr) * SW + j]);
                }
            }
#pragma unroll
            for (int o = 16; o > 0; o >>= 1)
#pragma unroll
                for (int rr = 0; rr < 4; rr++)
                    mx[rr] = fmaxf(mx[rr], __shfl_xor_sync(0xffffffffu, mx[rr], o));
#pragma unroll
            for (int rr = 0; rr < 4; rr++) sum[rr] = 0.f;
#pragma unroll
            for (int it = 0; it < 7; it++) {
                int j = lane + it * 32;
                if (j < NKC) {
#pragma unroll
                    for (int rr = 0; rr < 4; rr++) {
                        float* sp = &Ss[(warp * 4 + rr) * SW + j];
                        float e = fast_exp(*sp - mx[rr]);
                        *sp = rnd_tf32(e);
                        sum[rr] += e;
                    }
                }
            }
#pragma unroll
            for (int o = 16; o > 0; o >>= 1)
#pragma unroll
                for (int rr = 0; rr < 4; rr++)
                    sum[rr] += __shfl_xor_sync(0xffffffffu, sum[rr], o);
            if (lane == 0) {
#pragma unroll
                for (int rr = 0; rr < 4; rr++) Iv[warp * 4 + rr] = 1.f / sum[rr];
            }
        }
        __syncthreads();

        // ---- O = P @ V
        {
            float acc[2][4];
#pragma unroll
            for (int nt = 0; nt < 2; nt++)
#pragma unroll
                for (int c = 0; c < 4; c++) acc[nt][c] = 0.f;

            for (int ks = 0; ks < 25; ks++) {
                const int kc = ks * 8 + tig;
                const int r = wm * 16 + group;
                uint32_t af[4] = {
                    __float_as_uint(Ss[r * SW + kc]),
                    __float_as_uint(Ss[(r + 8) * SW + kc]),
                    __float_as_uint(Ss[r * SW + kc + 4]),
                    __float_as_uint(Ss[(r + 8) * SW + kc + 4]) };
#pragma unroll
                for (int nt = 0; nt < 2; nt++) {
                    int n = wn * 16 + nt * 8 + group;
                    uint32_t bf[2];
                    bf[0] = to_tf32_rn(Vn[(ks * 8 + tig) * VWN + n]);
                    bf[1] = to_tf32_rn(Vn[(ks * 8 + tig + 4) * VWN + n]);
                    mma_tf32(acc[nt], af, bf);
                }
            }
#pragma unroll
            for (int half = 0; half < 2; half++) {
                int rl = wm * 16 + group + half * 8;
                int qrow = qc * 64 + rl;
                if (qrow >= NKC) continue;
                float iv = Iv[rl];
                size_t base = ((size_t)bh * NOUT + 1 + (size_t)f * NKC + qrow) * 64;
#pragma unroll
                for (int nt = 0; nt < 2; nt++) {
                    int col = wn * 16 + nt * 8 + tig * 2;
                    __half2 w = __floats2half2_rn(acc[nt][half * 2] * iv,
                                                  acc[nt][half * 2 + 1] * iv);
                    *(__half2*)&g_attH[base + col] = w;
                }
            }
        }
        __syncthreads();
    }
}

// ======================= launch =======================
extern "C" void kernel_launch(void* const* d_in, const int* in_sizes, int n_in,
                              void* d_out, int out_size)
{
    const float* x        = (const float*)d_in[0];
    const float* question = (const float*)d_in[1];
    const float* Wq       = (const float*)d_in[2];
    const float* Wkv      = (const float*)d_in[3];
    const float* Wproj    = (const float*)d_in[4];
    const float* bproj    = (const float*)d_in[5];
    float* out = (float*)d_out;

    cudaFuncSetAttribute(fine_attn, cudaFuncAttributeMaxDynamicSharedMemorySize, FINE_SMEM);
    cudaFuncSetAttribute(gemm_tc<0>, cudaFuncAttributeMaxDynamicSharedMemorySize, GEMM_SMEM);
    cudaFuncSetAttribute(gemm_tc<1>, cudaFuncAttributeMaxDynamicSharedMemorySize, GEMM_SMEM);
    cudaFuncSetAttribute(gemm_tc<2>, cudaFuncAttributeMaxDynamicSharedMemorySize, GEMM_SMEM);

    // weight prep (one launch) + input fp16 converts
    transposeW<<<dim3(1536 / 32, 768 / 32, 3), 256>>>(Wq, Wkv, Wproj);
    {
        __half* qH; cudaGetSymbolAddress((void**)&qH, g_qH);
        __half* xH; cudaGetSymbolAddress((void**)&xH, g_xH);
        int gq = BB * NQ * (KDIM / 8);
        int gx = BB * NV * (KDIM / 8);
        convertH<<<(gq + 255) / 256, 256>>>(question, qH, gq, 0.125f);
        convertH<<<(gx + 255) / 256, 256>>>(x, xH, gx, 1.0f);
    }
    __half* qH; cudaGetSymbolAddress((void**)&qH, g_qH);
    __half* xH; cudaGetSymbolAddress((void**)&xH, g_xH);

    // q projection
    gemm_tc<0><<<dim3(768 / BN, (BB * NQ + BM - 1) / BM), 256, GEMM_SMEM>>>(
        qH, nullptr, nullptr, BB * NQ);

    // kv projection
    gemm_tc<1><<<dim3(1536 / BN, (BB * NV) / BM), 256, GEMM_SMEM>>>(
        xH, nullptr, nullptr, BB * NV);

    // attention
    cls_attn<<<BHN, 256>>>();
    fine_attn<<<BHN * FF, 512, FINE_SMEM>>>();

    // output projection
    gemm_tc<2><<<dim3(768 / BN, (BB * NOUT + BM - 1) / BM), 256, GEMM_SMEM>>>(
        nullptr, bproj, out, BB * NOUT);
}

// round 17
// speedup vs baseline: 1.5179x; 1.0823x over previous
#include <cuda_runtime.h>
#include <cuda_fp16.h>
#include <cstdint>
#include <math.h>

// Problem constants
#define BB    32
#define NQ    197
#define NV    1568
#define DIMD  768
#define HH    12
#define FF    8
#define NKC   196
#define NOUT  1569
#define BHN   384
#define KDIM  768

// ---------------- scratch (device globals) ----------------
__device__ __half g_qHh[(size_t)BHN * NQ * 64];        // q heads layout fp16 (scaled)
__device__ __half g_kH[(size_t)BHN * NV * 64];         // k heads layout fp16
__device__ __half g_vH[(size_t)BHN * NV * 64];         // v heads layout fp16
__device__ __half g_attH[(size_t)BHN * NOUT * 64];     // attention output fp16
__device__ __half g_qH[(size_t)BB * NQ * KDIM];        // question fp16, pre-scaled 0.125
__device__ __half g_xH[(size_t)BB * NV * KDIM];        // x fp16
__device__ __half g_wqTH[768 * 768];                   // W^T [N][K] fp16
__device__ __half g_wkvTH[1536 * 768];
__device__ __half g_wpTH[768 * 768];

// ======================= helpers =======================
__device__ __forceinline__ uint32_t smem_to_u32(const void* p) {
    uint32_t a;
    asm("{ .reg .u64 t; cvta.to.shared.u64 t, %1; cvt.u32.u64 %0, t; }" : "=r"(a) : "l"(p));
    return a;
}
__device__ __forceinline__ void cp_async16(uint32_t smem_addr, const void* gptr) {
    asm volatile("cp.async.cg.shared.global [%0], [%1], 16;"
                 :: "r"(smem_addr), "l"(gptr));
}
__device__ __forceinline__ void cp_async16p(uint32_t smem_addr, const void* gptr, bool pred) {
    int sz = pred ? 16 : 0;
    asm volatile("cp.async.cg.shared.global [%0], [%1], 16, %2;"
                 :: "r"(smem_addr), "l"(gptr), "r"(sz));
}
#define CP_COMMIT() asm volatile("cp.async.commit_group;" ::: "memory")
#define CP_WAIT(n)  asm volatile("cp.async.wait_group %0;" :: "n"(n) : "memory")

// fp16 m16n8k16
__device__ __forceinline__ void mma_f16(float* c, const uint32_t* a, const uint32_t* b) {
    asm volatile(
        "mma.sync.aligned.m16n8k16.row.col.f32.f16.f16.f32 "
        "{%0,%1,%2,%3}, {%4,%5,%6,%7}, {%8,%9}, {%0,%1,%2,%3};"
        : "+f"(c[0]), "+f"(c[1]), "+f"(c[2]), "+f"(c[3])
        : "r"(a[0]), "r"(a[1]), "r"(a[2]), "r"(a[3]), "r"(b[0]), "r"(b[1]));
}
__device__ __forceinline__ void ldmatrix_x4(uint32_t& r0, uint32_t& r1,
                                            uint32_t& r2, uint32_t& r3, uint32_t addr) {
    asm volatile("ldmatrix.sync.aligned.m8n8.x4.shared.b16 {%0,%1,%2,%3}, [%4];"
                 : "=r"(r0), "=r"(r1), "=r"(r2), "=r"(r3) : "r"(addr));
}

// FMA-pipe exp
__device__ __forceinline__ float fast_exp(float x) {
    x = fmaxf(x, -87.0f);
    float y = x * 1.4426950408889634f;
    float r = y + 12582912.0f;
    int   n = __float_as_int(r) - 0x4B400000;
    float f = y - (r - 12582912.0f);
    float p = 1.3333558146e-3f;
    p = fmaf(p, f, 9.6181291076e-3f);
    p = fmaf(p, f, 5.5504108664e-2f);
    p = fmaf(p, f, 2.4022650696e-1f);
    p = fmaf(p, f, 6.9314718056e-1f);
    p = fmaf(p, f, 1.0f);
    return __int_as_float(__float_as_int(p) + (n << 23));
}

// ======================= fp32 -> fp16 convert (+scale) =======================
__global__ __launch_bounds__(256)
void convertH(const float* __restrict__ src, __half* __restrict__ dst,
              int n8, float scale)
{
    int i = blockIdx.x * 256 + threadIdx.x;
    if (i >= n8) return;
    const float4* s = (const float4*)src + (size_t)i * 2;
    float4 v0 = s[0], v1 = s[1];
    __half2 h0 = __floats2half2_rn(v0.x * scale, v0.y * scale);
    __half2 h1 = __floats2half2_rn(v0.z * scale, v0.w * scale);
    __half2 h2 = __floats2half2_rn(v1.x * scale, v1.y * scale);
    __half2 h3 = __floats2half2_rn(v1.z * scale, v1.w * scale);
    uint4 o;
    o.x = *(uint32_t*)&h0; o.y = *(uint32_t*)&h1;
    o.z = *(uint32_t*)&h2; o.w = *(uint32_t*)&h3;
    ((uint4*)dst)[i] = o;
}

// ======================= weight transpose -> fp16 [N][K] =======================
__global__ __launch_bounds__(256)
void transposeW(const float* __restrict__ Wq, const float* __restrict__ Wkv,
                const float* __restrict__ Wproj)
{
    const int which = blockIdx.z;
    const float* src = (which == 0) ? Wq : (which == 1) ? Wkv : Wproj;
    __half* dst = (which == 0) ? g_wqTH : (which == 1) ? g_wkvTH : g_wpTH;
    const int N = (which == 1) ? 1536 : 768;
    const int K = 768;

    int bx = blockIdx.x * 32;
    int by = blockIdx.y * 32;
    if (bx >= N) return;

    __shared__ float t[32][33];
    int txl = threadIdx.x & 31;
    int tyl = threadIdx.x >> 5;
#pragma unroll
    for (int j = 0; j < 32; j += 8)
        t[tyl + j][txl] = src[(size_t)(by + tyl + j) * N + bx + txl];
    __syncthreads();
#pragma unroll
    for (int j = 0; j < 32; j += 8)
        dst[(size_t)(bx + tyl + j) * K + by + txl] = __float2half(t[txl][tyl + j]);
}

// ======================= fp16 mma.sync GEMM (R16 machinery, fp16 epilogues) ==========
constexpr int BM = 128, BN = 128, BK = 64;
constexpr int SK_H = 72;
constexpr int OP_HALFS = 128 * SK_H;
constexpr int STAGE_HALFS = 2 * OP_HALFS;
constexpr int GSTAGES = 3;
constexpr int GEMM_SMEM = GSTAGES * STAGE_HALFS * 2;   // 110592 bytes
constexpr int KT = KDIM / BK;                          // 12

template<int MODE>
__global__ __launch_bounds__(256, 2)
void gemm_tc(const __half* __restrict__ A, const float* __restrict__ bias,
             float* __restrict__ Cout, int M)
{
    extern __shared__ __half smh[];
    const uint32_t sb32 = smem_to_u32(smh);
    const int tid   = threadIdx.x;
    const int warp  = tid >> 5;
    const int lane  = tid & 31;
    const int group = lane >> 2;
    const int tig   = lane & 3;
    const int wm    = warp & 3;
    const int wn    = warp >> 2;
    const int row0  = blockIdx.y * BM;
    const int col0  = blockIdx.x * BN;

    const __half* BT = (MODE == 0) ? g_wqTH : (MODE == 1) ? g_wkvTH : g_wpTH;

    float acc[2][8][4];
#pragma unroll
    for (int mt = 0; mt < 2; mt++)
#pragma unroll
        for (int nt = 0; nt < 8; nt++)
#pragma unroll
            for (int c = 0; c < 4; c++) acc[mt][nt][c] = 0.f;

    const int lm_m = lane >> 3;
    const int lm_i = lane & 7;
    const int a_row = wm * 32 + (lm_m & 1) * 8 + lm_i;
    const int a_col = (lm_m >> 1) * 8;
    const int b_row = wn * 64 + (lm_m >> 1) * 8 + lm_i;
    const int b_col = (lm_m & 1) * 8;

    auto load_stage = [&](int kt, int s) {
        const uint32_t aoff = sb32 + (uint32_t)(s * STAGE_HALFS) * 2;
        const uint32_t boff = aoff + (uint32_t)OP_HALFS * 2;
        const int k0 = kt * BK;
#pragma unroll
        for (int it = 0; it < 4; it++) {
            int idx = tid + it * 256;
            int r = idx >> 3, ch = idx & 7;
            int grow = row0 + r;
            bool ok = grow < M;
            int gr = ok ? grow : 0;
            const __half* src;
            if (MODE == 2) {
                int b_ = gr / NOUT;
                int n_ = gr - b_ * NOUT;
                int kk = k0 + ch * 8;
                int h = kk >> 6, dd = kk & 63;
                src = &g_attH[(((size_t)(b_ * HH + h) * NOUT + n_) << 6) + dd];
            } else {
                src = &A[(size_t)gr * KDIM + k0 + ch * 8];
            }
            cp_async16p(aoff + (uint32_t)(r * SK_H + ch * 8) * 2, src, ok);
        }
#pragma unroll
        for (int it = 0; it < 4; it++) {
            int idx = tid + it * 256;
            int r = idx >> 3, ch = idx & 7;
            cp_async16(boff + (uint32_t)(r * SK_H + ch * 8) * 2,
                       &BT[(size_t)(col0 + r) * KDIM + k0 + ch * 8]);
        }
        CP_COMMIT();
    };

    load_stage(0, 0);
    load_stage(1, 1);

    for (int kt = 0; kt < KT; kt++) {
        if (kt < KT - 1) { CP_WAIT(1); } else { CP_WAIT(0); }
        __syncthreads();
        if (kt + 2 < KT) load_stage(kt + 2, (kt + 2) % GSTAGES);

        const uint32_t asb = sb32 + (uint32_t)((kt % GSTAGES) * STAGE_HALFS) * 2;
        const uint32_t bsb = asb + (uint32_t)OP_HALFS * 2;

#pragma unroll
        for (int s = 0; s < 4; s++) {
            const int kb = s * 16;
            uint32_t af[2][4];
#pragma unroll
            for (int mt = 0; mt < 2; mt++)
                ldmatrix_x4(af[mt][0], af[mt][1], af[mt][2], af[mt][3],
                            asb + (uint32_t)((a_row + mt * 16) * SK_H + kb + a_col) * 2);
#pragma unroll
            for (int p = 0; p < 4; p++) {
                uint32_t t0, t1, t2, t3;
                ldmatrix_x4(t0, t1, t2, t3,
                            bsb + (uint32_t)((b_row + p * 16) * SK_H + kb + b_col) * 2);
                uint32_t b0[2] = { t0, t1 };
                uint32_t b1[2] = { t2, t3 };
                mma_f16(acc[0][2 * p],     af[0], b0);
                mma_f16(acc[1][2 * p],     af[1], b0);
                mma_f16(acc[0][2 * p + 1], af[0], b1);
                mma_f16(acc[1][2 * p + 1], af[1], b1);
            }
        }
    }

    // ---- epilogue (fp16 q/k/v outputs)
#pragma unroll
    for (int mt = 0; mt < 2; mt++) {
#pragma unroll
        for (int half = 0; half < 2; half++) {
            int row = row0 + wm * 32 + mt * 16 + group + half * 8;
            if (row >= M) continue;
            int b_, n_;
            if (MODE == 0) { b_ = row / NQ;   n_ = row - b_ * NQ; }
            else if (MODE == 1) { b_ = row / NV; n_ = row - b_ * NV; }
            else { b_ = 0; n_ = 0; }
#pragma unroll
            for (int nt = 0; nt < 8; nt++) {
                int col = col0 + wn * 64 + nt * 8 + tig * 2;
                float v0 = acc[mt][nt][half * 2 + 0];
                float v1 = acc[mt][nt][half * 2 + 1];
                if (MODE == 0) {
                    int h = col >> 6, dd = col & 63;
                    *(__half2*)&g_qHh[(((size_t)(b_ * HH + h) * NQ + n_) << 6) + dd] =
                        __floats2half2_rn(v0, v1);
                } else if (MODE == 1) {
                    __half2 w = __floats2half2_rn(v0, v1);
                    if (col < DIMD) {
                        int h = col >> 6, dd = col & 63;
                        *(__half2*)&g_kH[(((size_t)(b_ * HH + h) * NV + n_) << 6) + dd] = w;
                    } else {
                        int c2 = col - DIMD;
                        int h = c2 >> 6, dd = c2 & 63;
                        *(__half2*)&g_vH[(((size_t)(b_ * HH + h) * NV + n_) << 6) + dd] = w;
                    }
                } else {
                    float2 w = make_float2(v0 + bias[col], v1 + bias[col + 1]);
                    *(float2*)&Cout[(size_t)row * DIMD + col] = w;
                }
            }
        }
    }
}

// ======================= cls-token attention (fp16 inputs) =======================
__global__ __launch_bounds__(256)
void cls_attn()
{
    __shared__ float qsh[64];
    __shared__ float ssh[NV];
    __shared__ float red[40];
    __shared__ float osh[4][64];

    const int bh   = blockIdx.x;
    const int tid  = threadIdx.x;
    const int lane = tid & 31;
    const int warp = tid >> 5;

    if (tid < 64) qsh[tid] = __half2float(g_qHh[((size_t)bh * NQ) * 64 + tid]);
    __syncthreads();

    for (int j = warp; j < NV; j += 8) {
        const __half* kr = &g_kH[((size_t)bh * NV + j) * 64];
        float p = qsh[lane] * __half2float(kr[lane])
                + qsh[lane + 32] * __half2float(kr[lane + 32]);
#pragma unroll
        for (int o = 16; o > 0; o >>= 1) p += __shfl_xor_sync(0xffffffffu, p, o);
        if (lane == 0) ssh[j] = p;
    }
    __syncthreads();

    float m = -1e30f;
    for (int j = tid; j < NV; j += 256) m = fmaxf(m, ssh[j]);
#pragma unroll
    for (int o = 16; o > 0; o >>= 1) m = fmaxf(m, __shfl_xor_sync(0xffffffffu, m, o));
    if (lane == 0) red[warp] = m;
    __syncthreads();
    if (tid == 0) {
        float mm = red[0];
        for (int w = 1; w < 8; w++) mm = fmaxf(mm, red[w]);
        red[32] = mm;
    }
    __syncthreads();
    m = red[32];

    float s = 0.f;
    for (int j = tid; j < NV; j += 256) {
        float e = fast_exp(ssh[j] - m);
        ssh[j] = e;
        s += e;
    }
#pragma unroll
    for (int o = 16; o > 0; o >>= 1) s += __shfl_xor_sync(0xffffffffu, s, o);
    if (lane == 0) red[8 + warp] = s;
    __syncthreads();
    if (tid == 0) {
        float ss = 0.f;
        for (int w = 0; w < 8; w++) ss += red[8 + w];
        red[33] = 1.f / ss;
    }
    __syncthreads();
    const float inv = red[33];

    const int g = tid >> 6, dd = tid & 63;
    float o = 0.f;
    for (int j = g; j < NV; j += 4)
        o = fmaf(ssh[j], __half2float(g_vH[((size_t)bh * NV + j) * 64 + dd]), o);
    osh[g][dd] = o;
    __syncthreads();
    if (tid < 64) {
        float r = (osh[0][tid] + osh[1][tid] + osh[2][tid] + osh[3][tid]) * inv;
        g_attH[((size_t)bh * NOUT) * 64 + tid] = __float2half(r);
    }
}

// ======================= fine attention — fp16 m16n8k16 ===========
constexpr int QW_H  = 72;    // Q  [64][72] halfs, 2 buffers
constexpr int KW_H  = 72;    // K  [224][72] halfs (rows 196..223 zero)
constexpr int VNW_H = 72;    // Vn [196][72] halfs natural
constexpr int VTW_H = 232;   // Vt [64][232] halfs transposed (keys 196..207 zero)
constexpr int SW_F  = 228;   // Ss [64][228] fp32
constexpr int PW_H  = 232;   // Ps [64][232] halfs (cols 196..207 zero)
constexpr int Q0_B = 0;
constexpr int Q1_B = Q0_B + 64 * QW_H * 2;     // 9216
constexpr int K_B  = Q1_B + 64 * QW_H * 2;     // 18432
constexpr int VN_B = K_B + 224 * KW_H * 2;     // 50688
constexpr int VT_B = VN_B + 196 * VNW_H * 2;   // 78912
constexpr int SS_B = VT_B + 64 * VTW_H * 2;    // 108608
constexpr int PS_B = SS_B + 64 * SW_F * 4;     // 166976
constexpr int IV_B = PS_B + 64 * PW_H * 2;     // 196672
constexpr int FINE_SMEM = IV_B + 256;          // 196928 bytes

__global__ __launch_bounds__(512, 1)
void fine_attn()
{
    extern __shared__ char smb[];
    __half* Ks = (__half*)(smb + K_B);
    __half* Vn = (__half*)(smb + VN_B);
    __half* Vt = (__half*)(smb + VT_B);
    float*  Ss = (float*) (smb + SS_B);
    __half* Ps = (__half*)(smb + PS_B);
    float*  Iv = (float*) (smb + IV_B);

    const int bh    = blockIdx.x >> 3;
    const int f     = blockIdx.x & 7;
    const int tid   = threadIdx.x;
    const int warp  = tid >> 5;
    const int lane  = tid & 31;
    const int group = lane >> 2;
    const int tig   = lane & 3;
    const int wm    = warp & 3;
    const int wn    = warp >> 2;

    const uint32_t sb32 = smem_to_u32(smb);
    const __half* kg = &g_kH[((size_t)bh * NV + (size_t)f * NKC) * 64];
    const __half* vg = &g_vH[((size_t)bh * NV + (size_t)f * NKC) * 64];
    const __half* qg = &g_qHh[((size_t)bh * NQ + 1) * 64];

    // ---- group 1: V natural + K (raw fp16 copies; 8 chunks of 16B per 64-half row)
    for (int idx = tid; idx < NKC * 8; idx += 512) {
        int j = idx >> 3, ch = idx & 7;
        cp_async16(sb32 + (uint32_t)(VN_B + (j * VNW_H + ch * 8) * 2), &vg[j * 64 + ch * 8]);
    }
    for (int idx = tid; idx < NKC * 8; idx += 512) {
        int j = idx >> 3, ch = idx & 7;
        cp_async16(sb32 + (uint32_t)(K_B + (j * KW_H + ch * 8) * 2), &kg[j * 64 + ch * 8]);
    }
    CP_COMMIT();

    // ---- group 2: Q chunk 0
    auto loadQ = [&](int qc, int buf) {
        const int rows = (qc == 3) ? (NKC - 192) : 64;   // 4 or 64
        const uint32_t qoff = sb32 + (uint32_t)(buf ? Q1_B : Q0_B);
        int r = tid >> 3, ch = tid & 7;                  // 512 chunks, one per thread
        cp_async16p(qoff + (uint32_t)((r * QW_H + ch * 8) * 2),
                    &qg[(size_t)(qc * 64 + r) * 64 + ch * 8], r < rows);
        CP_COMMIT();
    };
    loadQ(0, 0);

    // ---- K pad rows 196..223 zero (full 72-half rows = 9 x 16B)
    for (int idx = tid; idx < 28 * 9; idx += 512) {
        int r = 196 + idx / 9, c = (idx % 9) * 8;
        *(uint4*)((char*)Ks + (size_t)(r * KW_H + c) * 2) = make_uint4(0, 0, 0, 0);
    }

    CP_WAIT(1);            // V + K arrived (Q0 may still be in flight)
    __syncthreads();

    // ---- transpose Vn -> Vt (half2 packed), zero pad key cols 196..207
    for (int idx = tid; idx < 64 * 98; idx += 512) {
        int d = idx / 98, jp = idx % 98;
        __half a = Vn[(2 * jp) * VNW_H + d];
        __half b = Vn[(2 * jp + 1) * VNW_H + d];
        *(__half2*)&Vt[d * VTW_H + 2 * jp] = __halves2half2(a, b);
    }
    for (int idx = tid; idx < 64 * 6; idx += 512) {
        int d = idx / 6, c = (idx % 6) * 2;
        *(__half2*)&Vt[d * VTW_H + 196 + c] = __halves2half2(__float2half(0.f), __float2half(0.f));
    }

    for (int qc = 0; qc < 4; qc++) {
        if (qc < 3) loadQ(qc + 1, (qc + 1) & 1);
        if (qc < 3) { CP_WAIT(1); } else { CP_WAIT(0); }
        __syncthreads();   // orders: Q ready, Vt/K-pad writes (first iter), Ps reuse

        const __half* Qc = (const __half*)(smb + ((qc & 1) ? Q1_B : Q0_B));

        // ---- S = Q @ K^T : warps 4M x 4N, warp tile 16 x 56, 4 k16 steps
        {
            float acc[7][4];
#pragma unroll
            for (int nt = 0; nt < 7; nt++)
#pragma unroll
                for (int c = 0; c < 4; c++) acc[nt][c] = 0.f;

            const int r = wm * 16 + group;
#pragma unroll
            for (int ks = 0; ks < 4; ks++) {
                const int kh = ks * 16 + 2 * tig;
                uint32_t af[4];
                af[0] = *(const uint32_t*)&Qc[r * QW_H + kh];
                af[1] = *(const uint32_t*)&Qc[(r + 8) * QW_H + kh];
                af[2] = *(const uint32_t*)&Qc[r * QW_H + kh + 8];
                af[3] = *(const uint32_t*)&Qc[(r + 8) * QW_H + kh + 8];
#pragma unroll
                for (int nt = 0; nt < 7; nt++) {
                    int n = wn * 56 + nt * 8 + group;
                    uint32_t bf[2];
                    bf[0] = *(const uint32_t*)&Ks[n * KW_H + kh];
                    bf[1] = *(const uint32_t*)&Ks[n * KW_H + kh + 8];
                    mma_f16(acc[nt], af, bf);
                }
            }
#pragma unroll
            for (int nt = 0; nt < 7; nt++) {
                int n = wn * 56 + nt * 8 + tig * 2;
                *(float2*)&Ss[r * SW_F + n]       = make_float2(acc[nt][0], acc[nt][1]);
                *(float2*)&Ss[(r + 8) * SW_F + n] = make_float2(acc[nt][2], acc[nt][3]);
            }
        }
        __syncthreads();

        // ---- softmax: 4 rows/warp; writes fp16 P; zero-fills P cols 196..207
        {
            float mx[4], sum[4];
#pragma unroll
            for (int rr = 0; rr < 4; rr++) mx[rr] = -1e30f;
#pragma unroll
            for (int it = 0; it < 7; it++) {
                int j = lane + it * 32;
                if (j < NKC) {
#pragma unroll
                    for (int rr = 0; rr < 4; rr++)
                        mx[rr] = fmaxf(mx[rr], Ss[(warp * 4 + rr) * SW_F + j]);
                }
            }
#pragma unroll
            for (int o = 16; o > 0; o >>= 1)
#pragma unroll
                for (int rr = 0; rr < 4; rr++)
                    mx[rr] = fmaxf(mx[rr], __shfl_xor_sync(0xffffffffu, mx[rr], o));
#pragma unroll
            for (int rr = 0; rr < 4; rr++) sum[rr] = 0.f;
#pragma unroll
            for (int it = 0; it < 7; it++) {
                int j = lane + it * 32;
                if (j < NKC) {
#pragma unroll
                    for (int rr = 0; rr < 4; rr++) {
                        float e = fast_exp(Ss[(warp * 4 + rr) * SW_F + j] - mx[rr]);
                        Ps[(warp * 4 + rr) * PW_H + j] = __float2half(e);
                        sum[rr] += e;
                    }
                }
            }
            if (lane < 12) {
#pragma unroll
                for (int rr = 0; rr < 4; rr++)
                    Ps[(warp * 4 + rr) * PW_H + 196 + lane] = __float2half(0.f);
            }
#pragma unroll
            for (int o = 16; o > 0; o >>= 1)
#pragma unroll
                for (int rr = 0; rr < 4; rr++)
                    sum[rr] += __shfl_xor_sync(0xffffffffu, sum[rr], o);
            if (lane == 0) {
#pragma unroll
                for (int rr = 0; rr < 4; rr++) Iv[warp * 4 + rr] = 1.f / sum[rr];
            }
        }
        __syncthreads();

        // ---- O = P @ V : warps 4M x 4N, warp tile 16 x 16; 13 k16 steps over 208 keys
        {
            float acc[2][4];
#pragma unroll
            for (int nt = 0; nt < 2; nt++)
#pragma unroll
                for (int c = 0; c < 4; c++) acc[nt][c] = 0.f;

            const int r = wm * 16 + group;
#pragma unroll
            for (int ks = 0; ks < 13; ks++) {
                const int kh = ks * 16 + 2 * tig;
                uint32_t af[4];
                af[0] = *(const uint32_t*)&Ps[r * PW_H + kh];
                af[1] = *(const uint32_t*)&Ps[(r + 8) * PW_H + kh];
                af[2] = *(const uint32_t*)&Ps[r * PW_H + kh + 8];
                af[3] = *(const uint32_t*)&Ps[(r + 8) * PW_H + kh + 8];
#pragma unroll
                for (int nt = 0; nt < 2; nt++) {
                    int n = wn * 16 + nt * 8 + group;
                    uint32_t bf[2];
                    bf[0] = *(const uint32_t*)&Vt[n * VTW_H + kh];
                    bf[1] = *(const uint32_t*)&Vt[n * VTW_H + kh + 8];
                    mma_f16(acc[nt], af, bf);
                }
            }
#pragma unroll
            for (int half = 0; half < 2; half++) {
                int rl = wm * 16 + group + half * 8;
                int qrow = qc * 64 + rl;
                if (qrow >= NKC) continue;
                float iv = Iv[rl];
                size_t base = ((size_t)bh * NOUT + 1 + (size_t)f * NKC + qrow) * 64;
#pragma unroll
                for (int nt = 0; nt < 2; nt++) {
                    int col = wn * 16 + nt * 8 + tig * 2;
                    __half2 w = __floats2half2_rn(acc[nt][half * 2] * iv,
                                                  acc[nt][half * 2 + 1] * iv);
                    *(__half2*)&g_attH[base + col] = w;
                }
            }
        }
        __syncthreads();
    }
}

// ======================= launch =======================
extern "C" void kernel_launch(void* const* d_in, const int* in_sizes, int n_in,
                              void* d_out, int out_size)
{
    const float* x        = (const float*)d_in[0];
    const float* question = (const float*)d_in[1];
    const float* Wq       = (const float*)d_in[2];
    const float* Wkv      = (const float*)d_in[3];
    const float* Wproj    = (const float*)d_in[4];
    const float* bproj    = (const float*)d_in[5];
    float* out = (float*)d_out;

    cudaFuncSetAttribute(fine_attn, cudaFuncAttributeMaxDynamicSharedMemorySize, FINE_SMEM);
    cudaFuncSetAttribute(gemm_tc<0>, cudaFuncAttributeMaxDynamicSharedMemorySize, GEMM_SMEM);
    cudaFuncSetAttribute(gemm_tc<1>, cudaFuncAttributeMaxDynamicSharedMemorySize, GEMM_SMEM);
    cudaFuncSetAttribute(gemm_tc<2>, cudaFuncAttributeMaxDynamicSharedMemorySize, GEMM_SMEM);

    // weight prep (one launch) + input fp16 converts
    transposeW<<<dim3(1536 / 32, 768 / 32, 3), 256>>>(Wq, Wkv, Wproj);
    {
        __half* qH; cudaGetSymbolAddress((void**)&qH, g_qH);
        __half* xH; cudaGetSymbolAddress((void**)&xH, g_xH);
        int gq = BB * NQ * (KDIM / 8);
        int gx = BB * NV * (KDIM / 8);
        convertH<<<(gq + 255) / 256, 256>>>(question, qH, gq, 0.125f);
        convertH<<<(gx + 255) / 256, 256>>>(x, xH, gx, 1.0f);
    }
    __half* qH; cudaGetSymbolAddress((void**)&qH, g_qH);
    __half* xH; cudaGetSymbolAddress((void**)&xH, g_xH);

    // q projection
    gemm_tc<0><<<dim3(768 / BN, (BB * NQ + BM - 1) / BM), 256, GEMM_SMEM>>>(
        qH, nullptr, nullptr, BB * NQ);

    // kv projection
    gemm_tc<1><<<dim3(1536 / BN, (BB * NV) / BM), 256, GEMM_SMEM>>>(
        xH, nullptr, nullptr, BB * NV);

    // attention
    cls_attn<<<BHN, 256>>>();
    fine_attn<<<BHN * FF, 512, FINE_SMEM>>>();

    // output projection
    gemm_tc<2><<<dim3(768 / BN, (BB * NOUT + BM - 1) / BM), 256, GEMM_SMEM>>>(
        nullptr, bproj, out, BB * NOUT);
}